// round 5
// baseline (speedup 1.0000x reference)
#include <cuda_runtime.h>
#include <mma.h>
#include <math.h>
#include <stdint.h>

using namespace nvcuda;

#define B_   2
#define S_   2048
#define D_   1024
#define H_   16
#define HD_  64
#define KJL  32
#define M_   (B_*S_)
#define NF   2048         // folded qkv width: 512 qjl | 512 kjl | 1024 v

// ---- scratch (device globals: allocation is forbidden) --------------------
__device__ float g_wf[D_*NF];     // folded weights (tf32-rounded)
__device__ float g_bf[NF];        // folded bias (fp32)
__device__ float g_x2[M_*NF];     // folded qkv output
__device__ float g_ao[M_*D_];     // attention output (tf32-rounded)
__device__ float g_xr[M_*D_];     // tf32-rounded input X
__device__ float g_wpr[D_*D_];    // tf32-rounded W_proj

__device__ __forceinline__ float rtf32(float x) {
    asm("cvt.rna.tf32.f32 %0, %1;" : "=f"(x) : "f"(x));
    return x;
}
__device__ __forceinline__ void cpa16(uint32_t dst, const void* src) {
    asm volatile("cp.async.cg.shared.global [%0], [%1], 16;" :: "r"(dst), "l"(src));
}
__device__ __forceinline__ void cp_commit() {
    asm volatile("cp.async.commit_group;");
}
template<int N> __device__ __forceinline__ void cp_wait() {
    asm volatile("cp.async.wait_group %0;" :: "n"(N));
}

// ===========================================================================
// Prep: elementwise tf32 rounding into scratch
// ===========================================================================
__global__ void round_arr(const float* __restrict__ src, float* __restrict__ dst, int n)
{
    int i = blockIdx.x * 256 + threadIdx.x;
    if (i < n) dst[i] = rtf32(src[i]);
}

// ===========================================================================
// Fold S_proj into attention weights / bias (writes tf32-rounded weights)
// ===========================================================================
__global__ __launch_bounds__(256)
void fold_weights(const float* __restrict__ Wat, const float* __restrict__ Sp,
                  float* __restrict__ Wf)
{
    __shared__ float w[2048];
    __shared__ float sp[KJL][HD_];
    const int d = blockIdx.x, tid = threadIdx.x;
    for (int i = tid; i < 2048; i += 256) w[i] = Wat[(long)d * (3*D_) + i];
    for (int i = tid; i < KJL*HD_; i += 256) sp[i >> 6][i & 63] = Sp[i];
    __syncthreads();

    for (int o = tid; o < 1024; o += 256) {
        const int part = o >> 9;
        const int hk = o & 511, h = hk >> 5, k = hk & 31;
        const float* src = w + part * 1024 + h * HD_;
        float a = 0.f;
        #pragma unroll
        for (int e = 0; e < HD_; e++) a += src[e] * sp[k][e];
        Wf[(long)d * NF + part * 512 + hk] = rtf32(a);
    }
    for (int i = tid; i < 1024; i += 256)
        Wf[(long)d * NF + 1024 + i] = rtf32(Wat[(long)d * (3*D_) + 2048 + i]);
}

__global__ void fold_bias(const float* __restrict__ bat,
                          const float* __restrict__ Sp, float* __restrict__ bf)
{
    const int i = blockIdx.x * 256 + threadIdx.x;
    if (i >= NF) return;
    if (i < 1024) {
        const int part = i >> 9, hk = i & 511, h = hk >> 5, k = hk & 31;
        float a = 0.f;
        #pragma unroll
        for (int e = 0; e < HD_; e++) a += bat[part*1024 + h*HD_ + e] * Sp[k*HD_ + e];
        bf[i] = a;
    } else {
        bf[i] = bat[2048 + (i - 1024)];
    }
}

// ===========================================================================
// TF32 tensor-core GEMM + bias. Operands pre-rounded to tf32 in gmem.
// 128x128x16 block tile, 256 thr = 8 warps (4m x 2n), warp tile 32x64.
// 4-stage cp.async pipeline. Bias folded into acc init.
// ===========================================================================
#define GBM 128
#define GBN 128
#define GBK 16
#define LDA 20
#define LDB 132
#define STG 4
#define ASTAGE (GBM*LDA*4)      // bytes per A stage
#define BSTAGE (GBK*LDB*4)      // bytes per B stage

__global__ __launch_bounds__(256)
void tf32_gemm_bias(const float* __restrict__ A, const float* __restrict__ Bm,
                    const float* __restrict__ bias, float* __restrict__ C,
                    int M, int N, int K)
{
    extern __shared__ float dyn[];
    float* As = dyn;                        // [STG][GBM][LDA]
    float* Bs = dyn + STG*GBM*LDA;          // [STG][GBK][LDB]
    __shared__ float biasS[16][LDB];

    const int tid  = threadIdx.x;
    const int wid  = tid >> 5;
    const int brow = blockIdx.y * GBM;
    const int bcol = blockIdx.x * GBN;
    const int wm   = (wid & 3) * 32;
    const int wn   = (wid >> 2) * 64;

    for (int t = 0; t < 8; t++) {
        int idx = tid + t * 256;
        biasS[idx >> 7][idx & 127] = bias[bcol + (idx & 127)];
    }
    __syncthreads();

    wmma::fragment<wmma::accumulator, 16, 16, 8, float> acc[2][4];
    #pragma unroll
    for (int i = 0; i < 2; i++)
        #pragma unroll
        for (int j = 0; j < 4; j++)
            wmma::load_matrix_sync(acc[i][j], &biasS[0][wn + j*16], LDB,
                                   wmma::mem_row_major);

    const int ar0 = tid >> 2,  ac0 = (tid & 3) << 2;
    const int br0 = tid >> 5,  bc0 = (tid & 31) << 2;

    const float* Ap0 = A  + (long)(brow + ar0) * K + ac0;
    const float* Ap1 = A  + (long)(brow + ar0 + 64) * K + ac0;
    const float* Bp0 = Bm + (long)br0 * N + bcol + bc0;
    const float* Bp1 = Bm + (long)(br0 + 8) * N + bcol + bc0;

    const uint32_t sAs = (uint32_t)__cvta_generic_to_shared(As);
    const uint32_t sBs = (uint32_t)__cvta_generic_to_shared(Bs);
    const uint32_t aoff = (ar0 * LDA + ac0) * 4;
    const uint32_t boff = (br0 * LDB + bc0) * 4;

    const int KC = K / GBK;
    int fetch = 0;

    #pragma unroll
    for (int p = 0; p < STG - 1; p++) {
        uint32_t da = sAs + p * ASTAGE + aoff;
        uint32_t db = sBs + p * BSTAGE + boff;
        cpa16(da,                Ap0 + fetch * GBK);
        cpa16(da + 64*LDA*4,     Ap1 + fetch * GBK);
        cpa16(db,                Bp0 + (long)fetch * GBK * N);
        cpa16(db + 8*LDB*4,      Bp1 + (long)fetch * GBK * N);
        cp_commit();
        fetch++;
    }

    for (int c = 0; c < KC; c++) {
        cp_wait<STG - 2>();
        __syncthreads();

        const int s = c & (STG - 1);
        const float* Asb = As + s * GBM * LDA;
        const float* Bsb = Bs + s * GBK * LDB;

        #pragma unroll
        for (int kk = 0; kk < GBK; kk += 8) {
            wmma::fragment<wmma::matrix_a, 16, 16, 8, wmma::precision::tf32,
                           wmma::row_major> a_frag[2];
            wmma::fragment<wmma::matrix_b, 16, 16, 8, wmma::precision::tf32,
                           wmma::row_major> b_frag[4];
            #pragma unroll
            for (int i = 0; i < 2; i++)
                wmma::load_matrix_sync(a_frag[i], Asb + (wm + i*16)*LDA + kk, LDA);
            #pragma unroll
            for (int j = 0; j < 4; j++)
                wmma::load_matrix_sync(b_frag[j], Bsb + kk*LDB + wn + j*16, LDB);
            #pragma unroll
            for (int i = 0; i < 2; i++)
                #pragma unroll
                for (int j = 0; j < 4; j++)
                    wmma::mma_sync(acc[i][j], a_frag[i], b_frag[j], acc[i][j]);
        }

        if (fetch < KC) {
            const int p = fetch & (STG - 1);
            uint32_t da = sAs + p * ASTAGE + aoff;
            uint32_t db = sBs + p * BSTAGE + boff;
            cpa16(da,                Ap0 + fetch * GBK);
            cpa16(da + 64*LDA*4,     Ap1 + fetch * GBK);
            cpa16(db,                Bp0 + (long)fetch * GBK * N);
            cpa16(db + 8*LDB*4,      Bp1 + (long)fetch * GBK * N);
            fetch++;
        }
        cp_commit();    // empty groups at tail keep wait-count semantics
    }

    #pragma unroll
    for (int i = 0; i < 2; i++)
        #pragma unroll
        for (int j = 0; j < 4; j++)
            wmma::store_matrix_sync(
                C + (long)(brow + wm + i*16) * N + bcol + wn + j*16,
                acc[i][j], N, wmma::mem_row_major);
}

// ===========================================================================
// Tensor-core causal flash attention (m16n8k8 tf32), shuffle-based P reshape.
// Block: 128 thr = 4 warps, 64 queries/block; key tiles of 64.
// acc(g,t) holds P(g,2t),(g,2t+1),(g+8,2t),(g+8,2t+1); A-frag slice ks needs
// P(g, ks*8+t),(g+8, ks*8+t),(g, ks*8+t+4),(g+8, ks*8+t+4) -> intra-quad shfl.
// Heavy q-tiles scheduled first (reverse blockIdx.x).
// grid = (S/64, H, B)
// ===========================================================================
#define LDK 36
#define LDV 68

__device__ __forceinline__ void mma8(float4& d, const uint32_t* a,
                                     uint32_t b0, uint32_t b1)
{
    asm volatile(
        "mma.sync.aligned.m16n8k8.row.col.f32.tf32.tf32.f32 "
        "{%0,%1,%2,%3},{%4,%5,%6,%7},{%8,%9},{%0,%1,%2,%3};"
        : "+f"(d.x), "+f"(d.y), "+f"(d.z), "+f"(d.w)
        : "r"(a[0]), "r"(a[1]), "r"(a[2]), "r"(a[3]), "r"(b0), "r"(b1));
}

__global__ __launch_bounds__(128)
void attn_mma(const float* __restrict__ x2, float* __restrict__ ao)
{
    __shared__ float Ks[64 * LDK];     // also Q staging ([64][32] fits)
    __shared__ float Vs[64 * LDV];

    const int tid  = threadIdx.x;
    const int w    = tid >> 5;
    const int lane = tid & 31;
    const int g    = lane >> 2;
    const int t    = lane & 3;
    const int h    = blockIdx.y;
    const int b    = blockIdx.z;
    const int qt   = gridDim.x - 1 - blockIdx.x;   // heavy tiles first
    const int q0   = qt * 64;

    // ---- stage Q [64][32] (tf32-rounded) into Ks --------------------------
    {
        const float* qb = x2 + (long)(b * S_ + q0) * NF + h * KJL;
        #pragma unroll
        for (int i = 0; i < 4; i++) {
            int idx = tid + i * 128;
            int r = idx >> 3, c = (idx & 7) << 2;
            float4 v = *(const float4*)(qb + (long)r * NF + c);
            Ks[r*32 + c + 0] = rtf32(v.x);
            Ks[r*32 + c + 1] = rtf32(v.y);
            Ks[r*32 + c + 2] = rtf32(v.z);
            Ks[r*32 + c + 3] = rtf32(v.w);
        }
    }
    __syncthreads();

    uint32_t qf[4][4];
    #pragma unroll
    for (int ks = 0; ks < 4; ks++) {
        qf[ks][0] = __float_as_uint(Ks[(w*16 + g    )*32 + ks*8 + t    ]);
        qf[ks][1] = __float_as_uint(Ks[(w*16 + g + 8)*32 + ks*8 + t    ]);
        qf[ks][2] = __float_as_uint(Ks[(w*16 + g    )*32 + ks*8 + t + 4]);
        qf[ks][3] = __float_as_uint(Ks[(w*16 + g + 8)*32 + ks*8 + t + 4]);
    }
    __syncthreads();   // all warps done reading Q before Ks is overwritten

    float4 oacc[8];
    #pragma unroll
    for (int nt = 0; nt < 8; nt++) oacc[nt] = make_float4(0.f, 0.f, 0.f, 0.f);
    float m0 = -1e30f, m1 = -1e30f, l0 = 0.f, l1 = 0.f;

    const int R0 = q0 + w*16 + g;
    const int R1 = R0 + 8;
    const int nkt = qt + 1;
    const int lq0 = (lane & ~3) | (t >> 1);   // shuffle source lanes
    const int lq1 = lq0 + 2;

    for (int kt = 0; kt < nkt; kt++) {
        // ---- load K tile [64][32] and V tile [64][64], tf32-rounded -------
        {
            const float* kb = x2 + (long)(b*S_ + kt*64) * NF + 512 + h*KJL;
            #pragma unroll
            for (int i = 0; i < 4; i++) {
                int idx = tid + i * 128;
                int r = idx >> 3, c = (idx & 7) << 2;
                float4 v = *(const float4*)(kb + (long)r * NF + c);
                Ks[r*LDK + c + 0] = rtf32(v.x);
                Ks[r*LDK + c + 1] = rtf32(v.y);
                Ks[r*LDK + c + 2] = rtf32(v.z);
                Ks[r*LDK + c + 3] = rtf32(v.w);
            }
            const float* vb = x2 + (long)(b*S_ + kt*64) * NF + 1024 + h*HD_;
            #pragma unroll
            for (int i = 0; i < 8; i++) {
                int idx = tid + i * 128;
                int r = idx >> 4, c = (idx & 15) << 2;
                float4 v = *(const float4*)(vb + (long)r * NF + c);
                Vs[r*LDV + c + 0] = rtf32(v.x);
                Vs[r*LDV + c + 1] = rtf32(v.y);
                Vs[r*LDV + c + 2] = rtf32(v.z);
                Vs[r*LDV + c + 3] = rtf32(v.w);
            }
        }
        __syncthreads();

        // ---- S = Q @ K^T ---------------------------------------------------
        float4 sa[8];
        #pragma unroll
        for (int nt = 0; nt < 8; nt++) {
            sa[nt] = make_float4(0.f, 0.f, 0.f, 0.f);
            #pragma unroll
            for (int ks = 0; ks < 4; ks++) {
                uint32_t b0 = __float_as_uint(Ks[(nt*8 + g)*LDK + ks*8 + t    ]);
                uint32_t b1 = __float_as_uint(Ks[(nt*8 + g)*LDK + ks*8 + t + 4]);
                mma8(sa[nt], qf[ks], b0, b1);
            }
        }

        // ---- scale + causal mask + online softmax --------------------------
        float mx0 = -1e30f, mx1 = -1e30f;
        #pragma unroll
        for (int nt = 0; nt < 8; nt++) {
            const int c0 = kt*64 + nt*8 + 2*t;
            const int c1 = c0 + 1;
            sa[nt].x = (c0 <= R0) ? sa[nt].x * 0.125f : -1e30f;
            sa[nt].y = (c1 <= R0) ? sa[nt].y * 0.125f : -1e30f;
            sa[nt].z = (c0 <= R1) ? sa[nt].z * 0.125f : -1e30f;
            sa[nt].w = (c1 <= R1) ? sa[nt].w * 0.125f : -1e30f;
            mx0 = fmaxf(mx0, fmaxf(sa[nt].x, sa[nt].y));
            mx1 = fmaxf(mx1, fmaxf(sa[nt].z, sa[nt].w));
        }
        mx0 = fmaxf(mx0, __shfl_xor_sync(0xffffffff, mx0, 1));
        mx0 = fmaxf(mx0, __shfl_xor_sync(0xffffffff, mx0, 2));
        mx1 = fmaxf(mx1, __shfl_xor_sync(0xffffffff, mx1, 1));
        mx1 = fmaxf(mx1, __shfl_xor_sync(0xffffffff, mx1, 2));

        const float nm0 = fmaxf(m0, mx0);
        const float nm1 = fmaxf(m1, mx1);
        const float sc0 = __expf(m0 - nm0);
        const float sc1 = __expf(m1 - nm1);

        float ps0 = 0.f, ps1 = 0.f;
        #pragma unroll
        for (int nt = 0; nt < 8; nt++) {
            sa[nt].x = __expf(sa[nt].x - nm0);
            sa[nt].y = __expf(sa[nt].y - nm0);
            sa[nt].z = __expf(sa[nt].z - nm1);
            sa[nt].w = __expf(sa[nt].w - nm1);
            ps0 += sa[nt].x + sa[nt].y;
            ps1 += sa[nt].z + sa[nt].w;
        }
        ps0 += __shfl_xor_sync(0xffffffff, ps0, 1);
        ps0 += __shfl_xor_sync(0xffffffff, ps0, 2);
        ps1 += __shfl_xor_sync(0xffffffff, ps1, 1);
        ps1 += __shfl_xor_sync(0xffffffff, ps1, 2);

        l0 = l0 * sc0 + ps0;  m0 = nm0;
        l1 = l1 * sc1 + ps1;  m1 = nm1;

        #pragma unroll
        for (int nt = 0; nt < 8; nt++) {
            oacc[nt].x *= sc0;  oacc[nt].y *= sc0;
            oacc[nt].z *= sc1;  oacc[nt].w *= sc1;
        }

        // ---- O += P @ V : shuffle acc layout -> A-frag layout --------------
        #pragma unroll
        for (int ks = 0; ks < 8; ks++) {
            float x0 = __shfl_sync(0xffffffff, sa[ks].x, lq0);
            float y0 = __shfl_sync(0xffffffff, sa[ks].y, lq0);
            float z0 = __shfl_sync(0xffffffff, sa[ks].z, lq0);
            float w0 = __shfl_sync(0xffffffff, sa[ks].w, lq0);
            float x1 = __shfl_sync(0xffffffff, sa[ks].x, lq1);
            float y1 = __shfl_sync(0xffffffff, sa[ks].y, lq1);
            float z1 = __shfl_sync(0xffffffff, sa[ks].z, lq1);
            float w1 = __shfl_sync(0xffffffff, sa[ks].w, lq1);
            uint32_t pa[4];
            pa[0] = __float_as_uint(rtf32((t & 1) ? y0 : x0));
            pa[1] = __float_as_uint(rtf32((t & 1) ? w0 : z0));
            pa[2] = __float_as_uint(rtf32((t & 1) ? y1 : x1));
            pa[3] = __float_as_uint(rtf32((t & 1) ? w1 : z1));

            const int kr0 = (ks*8 + t    ) * LDV + g;
            const int kr1 = (ks*8 + t + 4) * LDV + g;
            #pragma unroll
            for (int nt = 0; nt < 8; nt++) {
                uint32_t b0 = __float_as_uint(Vs[kr0 + nt*8]);
                uint32_t b1 = __float_as_uint(Vs[kr1 + nt*8]);
                mma8(oacc[nt], pa, b0, b1);
            }
        }
        __syncthreads();
    }

    // ---- normalize + store (tf32-rounded for the following GEMM) ----------
    const float inv0 = 1.f / l0;
    const float inv1 = 1.f / l1;
    float* o0 = ao + (long)(b*S_ + R0) * D_ + h*HD_;
    float* o1 = ao + (long)(b*S_ + R1) * D_ + h*HD_;
    #pragma unroll
    for (int nt = 0; nt < 8; nt++) {
        *(float2*)(o0 + nt*8 + 2*t) =
            make_float2(rtf32(oacc[nt].x * inv0), rtf32(oacc[nt].y * inv0));
        *(float2*)(o1 + nt*8 + 2*t) =
            make_float2(rtf32(oacc[nt].z * inv1), rtf32(oacc[nt].w * inv1));
    }
}

// ===========================================================================
extern "C" void kernel_launch(void* const* d_in, const int* in_sizes, int n_in,
                              void* d_out, int out_size)
{
    const float* X    = (const float*)d_in[0];
    const float* Wat  = (const float*)d_in[1];
    const float* bat  = (const float*)d_in[2];
    const float* Sp   = (const float*)d_in[3];
    const float* Wp   = (const float*)d_in[4];
    const float* bp   = (const float*)d_in[5];
    float* out = (float*)d_out;

    float *wf, *bf, *x2, *ao, *xr, *wpr;
    cudaGetSymbolAddress((void**)&wf,  g_wf);
    cudaGetSymbolAddress((void**)&bf,  g_bf);
    cudaGetSymbolAddress((void**)&x2,  g_x2);
    cudaGetSymbolAddress((void**)&ao,  g_ao);
    cudaGetSymbolAddress((void**)&xr,  g_xr);
    cudaGetSymbolAddress((void**)&wpr, g_wpr);

    const int dynSmem = STG * (GBM*LDA + GBK*LDB) * 4;
    cudaFuncSetAttribute(tf32_gemm_bias,
                         cudaFuncAttributeMaxDynamicSharedMemorySize, dynSmem);

    // 0. prep: tf32-round GEMM operands; fold S_proj
    round_arr<<<(M_*D_ + 255)/256, 256>>>(X,  xr,  M_*D_);
    round_arr<<<(D_*D_ + 255)/256, 256>>>(Wp, wpr, D_*D_);
    fold_weights<<<D_, 256>>>(Wat, Sp, wf);
    fold_bias<<<NF/256, 256>>>(bat, Sp, bf);

    // 1. folded QKV GEMM
    dim3 g1(NF/GBN, M_/GBM);
    tf32_gemm_bias<<<g1, 256, dynSmem>>>(xr, wf, bf, x2, M_, NF, D_);

    // 2. causal flash attention
    dim3 g3(S_/64, H_, B_);
    attn_mma<<<g3, 128>>>(x2, ao);

    // 3. output projection GEMM
    dim3 g4(D_/GBN, M_/GBM);
    tf32_gemm_bias<<<g4, 256, dynSmem>>>(ao, wpr, bp, out, M_, D_, D_);
}

// round 6
// speedup vs baseline: 1.6132x; 1.6132x over previous
#include <cuda_runtime.h>
#include <mma.h>
#include <math.h>
#include <stdint.h>

using namespace nvcuda;

#define B_   2
#define S_   2048
#define D_   1024
#define H_   16
#define HD_  64
#define KJL  32
#define M_   (B_*S_)
#define NF   2048         // folded qkv width: 512 qjl | 512 kjl | 1024 v

// ---- scratch (device globals: allocation is forbidden) --------------------
__device__ float g_wf[D_*NF];     // folded weights (tf32-rounded)
__device__ float g_bf[NF];        // folded bias (fp32)
__device__ float g_x2[M_*NF];     // folded qkv output
__device__ float g_ao[M_*D_];     // attention output (tf32-rounded)
__device__ float g_xr[M_*D_];     // tf32-rounded input X
__device__ float g_wpr[D_*D_];    // tf32-rounded W_proj

__device__ __forceinline__ float rtf32(float x) {
    asm("cvt.rna.tf32.f32 %0, %1;" : "=f"(x) : "f"(x));
    return x;
}
__device__ __forceinline__ void cpa16(uint32_t dst, const void* src) {
    asm volatile("cp.async.cg.shared.global [%0], [%1], 16;" :: "r"(dst), "l"(src));
}
__device__ __forceinline__ void cp_commit() {
    asm volatile("cp.async.commit_group;");
}
template<int N> __device__ __forceinline__ void cp_wait() {
    asm volatile("cp.async.wait_group %0;" :: "n"(N));
}

// ===========================================================================
// Prep: tf32-round X and W_proj in one launch
// ===========================================================================
__global__ void round_prep(const float* __restrict__ X, const float* __restrict__ Wp,
                           float* __restrict__ xr, float* __restrict__ wpr)
{
    int i = blockIdx.x * 256 + threadIdx.x;
    if (i < M_*D_) xr[i] = rtf32(X[i]);
    else {
        int j = i - M_*D_;
        if (j < D_*D_) wpr[j] = rtf32(Wp[j]);
    }
}

// ===========================================================================
// Fold S_proj into attention weights (tf32-rounded) + bias (block D_)
// ===========================================================================
__global__ __launch_bounds__(256)
void fold_weights(const float* __restrict__ Wat, const float* __restrict__ bat,
                  const float* __restrict__ Sp,
                  float* __restrict__ Wf, float* __restrict__ bf)
{
    const int tid = threadIdx.x;

    if (blockIdx.x == D_) {               // bias block
        for (int i = tid; i < NF; i += 256) {
            if (i < 1024) {
                const int part = i >> 9, hk = i & 511, h = hk >> 5, k = hk & 31;
                float a = 0.f;
                #pragma unroll
                for (int e = 0; e < HD_; e++)
                    a += bat[part*1024 + h*HD_ + e] * Sp[k*HD_ + e];
                bf[i] = a;
            } else {
                bf[i] = bat[2048 + (i - 1024)];
            }
        }
        return;
    }

    __shared__ float w[2048];
    __shared__ float sp[KJL][HD_];
    const int d = blockIdx.x;
    for (int i = tid; i < 2048; i += 256) w[i] = Wat[(long)d * (3*D_) + i];
    for (int i = tid; i < KJL*HD_; i += 256) sp[i >> 6][i & 63] = Sp[i];
    __syncthreads();

    for (int o = tid; o < 1024; o += 256) {
        const int part = o >> 9;
        const int hk = o & 511, h = hk >> 5, k = hk & 31;
        const float* src = w + part * 1024 + h * HD_;
        float a = 0.f;
        #pragma unroll
        for (int e = 0; e < HD_; e++) a += src[e] * sp[k][e];
        Wf[(long)d * NF + part * 512 + hk] = rtf32(a);
    }
    for (int i = tid; i < 1024; i += 256)
        Wf[(long)d * NF + 1024 + i] = rtf32(Wat[(long)d * (3*D_) + 2048 + i]);
}

// ===========================================================================
// TF32 tensor-core GEMM + bias. Operands pre-rounded to tf32 in gmem.
// 128x128x16 block tile, 256 thr = 8 warps (4m x 2n), warp tile 32x64.
// 3-stage cp.async pipeline; sized for 2 blocks/SM (smem 64.5KB, regs<=128).
// ===========================================================================
#define GBM 128
#define GBN 128
#define GBK 16
#define LDA 20
#define LDB 132
#define STG 3
#define ASTAGE (GBM*LDA*4)
#define BSTAGE (GBK*LDB*4)

__global__ __launch_bounds__(256, 2)
void tf32_gemm_bias(const float* __restrict__ A, const float* __restrict__ Bm,
                    const float* __restrict__ bias, float* __restrict__ C,
                    int M, int N, int K)
{
    extern __shared__ float dyn[];
    float* As = dyn;                        // [STG][GBM][LDA]
    float* Bs = dyn + STG*GBM*LDA;          // [STG][GBK][LDB]
    __shared__ float biasS[16][LDB];

    const int tid  = threadIdx.x;
    const int wid  = tid >> 5;
    const int brow = blockIdx.y * GBM;
    const int bcol = blockIdx.x * GBN;
    const int wm   = (wid & 3) * 32;
    const int wn   = (wid >> 2) * 64;

    for (int t = 0; t < 8; t++) {
        int idx = tid + t * 256;
        biasS[idx >> 7][idx & 127] = bias[bcol + (idx & 127)];
    }
    __syncthreads();

    wmma::fragment<wmma::accumulator, 16, 16, 8, float> acc[2][4];
    #pragma unroll
    for (int i = 0; i < 2; i++)
        #pragma unroll
        for (int j = 0; j < 4; j++)
            wmma::load_matrix_sync(acc[i][j], &biasS[0][wn + j*16], LDB,
                                   wmma::mem_row_major);

    const int ar0 = tid >> 2,  ac0 = (tid & 3) << 2;
    const int br0 = tid >> 5,  bc0 = (tid & 31) << 2;

    const float* Ap0 = A  + (long)(brow + ar0) * K + ac0;
    const float* Ap1 = A  + (long)(brow + ar0 + 64) * K + ac0;
    const float* Bp0 = Bm + (long)br0 * N + bcol + bc0;
    const float* Bp1 = Bm + (long)(br0 + 8) * N + bcol + bc0;

    const uint32_t sAs = (uint32_t)__cvta_generic_to_shared(As);
    const uint32_t sBs = (uint32_t)__cvta_generic_to_shared(Bs);
    const uint32_t aoff = (ar0 * LDA + ac0) * 4;
    const uint32_t boff = (br0 * LDB + bc0) * 4;

    const int KC = K / GBK;
    int fetch = 0;

    #pragma unroll
    for (int p = 0; p < STG - 1; p++) {
        uint32_t da = sAs + p * ASTAGE + aoff;
        uint32_t db = sBs + p * BSTAGE + boff;
        cpa16(da,            Ap0 + fetch * GBK);
        cpa16(da + 64*LDA*4, Ap1 + fetch * GBK);
        cpa16(db,            Bp0 + (long)fetch * GBK * N);
        cpa16(db + 8*LDB*4,  Bp1 + (long)fetch * GBK * N);
        cp_commit();
        fetch++;
    }

    int s = 0;
    for (int c = 0; c < KC; c++) {
        cp_wait<STG - 2>();
        __syncthreads();

        const float* Asb = As + s * GBM * LDA;
        const float* Bsb = Bs + s * GBK * LDB;

        #pragma unroll
        for (int kk = 0; kk < GBK; kk += 8) {
            wmma::fragment<wmma::matrix_a, 16, 16, 8, wmma::precision::tf32,
                           wmma::row_major> a_frag[2];
            wmma::fragment<wmma::matrix_b, 16, 16, 8, wmma::precision::tf32,
                           wmma::row_major> b_frag[4];
            #pragma unroll
            for (int i = 0; i < 2; i++)
                wmma::load_matrix_sync(a_frag[i], Asb + (wm + i*16)*LDA + kk, LDA);
            #pragma unroll
            for (int j = 0; j < 4; j++)
                wmma::load_matrix_sync(b_frag[j], Bsb + kk*LDB + wn + j*16, LDB);
            #pragma unroll
            for (int i = 0; i < 2; i++)
                #pragma unroll
                for (int j = 0; j < 4; j++)
                    wmma::mma_sync(acc[i][j], a_frag[i], b_frag[j], acc[i][j]);
        }

        if (fetch < KC) {
            const int p = (s + STG - 1) >= STG ? s - 1 : s + STG - 1;  // (c+STG-1)%STG
            uint32_t da = sAs + p * ASTAGE + aoff;
            uint32_t db = sBs + p * BSTAGE + boff;
            cpa16(da,            Ap0 + fetch * GBK);
            cpa16(da + 64*LDA*4, Ap1 + fetch * GBK);
            cpa16(db,            Bp0 + (long)fetch * GBK * N);
            cpa16(db + 8*LDB*4,  Bp1 + (long)fetch * GBK * N);
            fetch++;
        }
        cp_commit();
        s = (s + 1 == STG) ? 0 : s + 1;
    }

    #pragma unroll
    for (int i = 0; i < 2; i++)
        #pragma unroll
        for (int j = 0; j < 4; j++)
            wmma::store_matrix_sync(
                C + (long)(brow + wm + i*16) * N + bcol + wn + j*16,
                acc[i][j], N, wmma::mem_row_major);
}

// ===========================================================================
// Tensor-core causal flash attention (m16n8k8 tf32), shuffle-based P reshape.
// grid = (S/64, H, B), 128 thr = 4 warps, heavy q-tiles first.
// ===========================================================================
#define LDK 36
#define LDV 68

__device__ __forceinline__ void mma8(float4& d, const uint32_t* a,
                                     uint32_t b0, uint32_t b1)
{
    asm volatile(
        "mma.sync.aligned.m16n8k8.row.col.f32.tf32.tf32.f32 "
        "{%0,%1,%2,%3},{%4,%5,%6,%7},{%8,%9},{%0,%1,%2,%3};"
        : "+f"(d.x), "+f"(d.y), "+f"(d.z), "+f"(d.w)
        : "r"(a[0]), "r"(a[1]), "r"(a[2]), "r"(a[3]), "r"(b0), "r"(b1));
}

__global__ __launch_bounds__(128)
void attn_mma(const float* __restrict__ x2, float* __restrict__ ao)
{
    __shared__ float Ks[64 * LDK];     // also Q staging
    __shared__ float Vs[64 * LDV];

    const int tid  = threadIdx.x;
    const int w    = tid >> 5;
    const int lane = tid & 31;
    const int g    = lane >> 2;
    const int t    = lane & 3;
    const int h    = blockIdx.y;
    const int b    = blockIdx.z;
    const int qt   = gridDim.x - 1 - blockIdx.x;
    const int q0   = qt * 64;

    {
        const float* qb = x2 + (long)(b * S_ + q0) * NF + h * KJL;
        #pragma unroll
        for (int i = 0; i < 4; i++) {
            int idx = tid + i * 128;
            int r = idx >> 3, c = (idx & 7) << 2;
            float4 v = *(const float4*)(qb + (long)r * NF + c);
            Ks[r*32 + c + 0] = rtf32(v.x);
            Ks[r*32 + c + 1] = rtf32(v.y);
            Ks[r*32 + c + 2] = rtf32(v.z);
            Ks[r*32 + c + 3] = rtf32(v.w);
        }
    }
    __syncthreads();

    uint32_t qf[4][4];
    #pragma unroll
    for (int ks = 0; ks < 4; ks++) {
        qf[ks][0] = __float_as_uint(Ks[(w*16 + g    )*32 + ks*8 + t    ]);
        qf[ks][1] = __float_as_uint(Ks[(w*16 + g + 8)*32 + ks*8 + t    ]);
        qf[ks][2] = __float_as_uint(Ks[(w*16 + g    )*32 + ks*8 + t + 4]);
        qf[ks][3] = __float_as_uint(Ks[(w*16 + g + 8)*32 + ks*8 + t + 4]);
    }
    __syncthreads();

    float4 oacc[8];
    #pragma unroll
    for (int nt = 0; nt < 8; nt++) oacc[nt] = make_float4(0.f, 0.f, 0.f, 0.f);
    float m0 = -1e30f, m1 = -1e30f, l0 = 0.f, l1 = 0.f;

    const int R0 = q0 + w*16 + g;
    const int R1 = R0 + 8;
    const int nkt = qt + 1;
    const int lq0 = (lane & ~3) | (t >> 1);
    const int lq1 = lq0 + 2;

    for (int kt = 0; kt < nkt; kt++) {
        {
            const float* kb = x2 + (long)(b*S_ + kt*64) * NF + 512 + h*KJL;
            #pragma unroll
            for (int i = 0; i < 4; i++) {
                int idx = tid + i * 128;
                int r = idx >> 3, c = (idx & 7) << 2;
                float4 v = *(const float4*)(kb + (long)r * NF + c);
                Ks[r*LDK + c + 0] = rtf32(v.x);
                Ks[r*LDK + c + 1] = rtf32(v.y);
                Ks[r*LDK + c + 2] = rtf32(v.z);
                Ks[r*LDK + c + 3] = rtf32(v.w);
            }
            const float* vb = x2 + (long)(b*S_ + kt*64) * NF + 1024 + h*HD_;
            #pragma unroll
            for (int i = 0; i < 8; i++) {
                int idx = tid + i * 128;
                int r = idx >> 4, c = (idx & 15) << 2;
                float4 v = *(const float4*)(vb + (long)r * NF + c);
                Vs[r*LDV + c + 0] = rtf32(v.x);
                Vs[r*LDV + c + 1] = rtf32(v.y);
                Vs[r*LDV + c + 2] = rtf32(v.z);
                Vs[r*LDV + c + 3] = rtf32(v.w);
            }
        }
        __syncthreads();

        float4 sa[8];
        #pragma unroll
        for (int nt = 0; nt < 8; nt++) {
            sa[nt] = make_float4(0.f, 0.f, 0.f, 0.f);
            #pragma unroll
            for (int ks = 0; ks < 4; ks++) {
                uint32_t b0 = __float_as_uint(Ks[(nt*8 + g)*LDK + ks*8 + t    ]);
                uint32_t b1 = __float_as_uint(Ks[(nt*8 + g)*LDK + ks*8 + t + 4]);
                mma8(sa[nt], qf[ks], b0, b1);
            }
        }

        float mx0 = -1e30f, mx1 = -1e30f;
        #pragma unroll
        for (int nt = 0; nt < 8; nt++) {
            const int c0 = kt*64 + nt*8 + 2*t;
            const int c1 = c0 + 1;
            sa[nt].x = (c0 <= R0) ? sa[nt].x * 0.125f : -1e30f;
            sa[nt].y = (c1 <= R0) ? sa[nt].y * 0.125f : -1e30f;
            sa[nt].z = (c0 <= R1) ? sa[nt].z * 0.125f : -1e30f;
            sa[nt].w = (c1 <= R1) ? sa[nt].w * 0.125f : -1e30f;
            mx0 = fmaxf(mx0, fmaxf(sa[nt].x, sa[nt].y));
            mx1 = fmaxf(mx1, fmaxf(sa[nt].z, sa[nt].w));
        }
        mx0 = fmaxf(mx0, __shfl_xor_sync(0xffffffff, mx0, 1));
        mx0 = fmaxf(mx0, __shfl_xor_sync(0xffffffff, mx0, 2));
        mx1 = fmaxf(mx1, __shfl_xor_sync(0xffffffff, mx1, 1));
        mx1 = fmaxf(mx1, __shfl_xor_sync(0xffffffff, mx1, 2));

        const float nm0 = fmaxf(m0, mx0);
        const float nm1 = fmaxf(m1, mx1);
        const float sc0 = __expf(m0 - nm0);
        const float sc1 = __expf(m1 - nm1);

        float ps0 = 0.f, ps1 = 0.f;
        #pragma unroll
        for (int nt = 0; nt < 8; nt++) {
            sa[nt].x = __expf(sa[nt].x - nm0);
            sa[nt].y = __expf(sa[nt].y - nm0);
            sa[nt].z = __expf(sa[nt].z - nm1);
            sa[nt].w = __expf(sa[nt].w - nm1);
            ps0 += sa[nt].x + sa[nt].y;
            ps1 += sa[nt].z + sa[nt].w;
        }
        ps0 += __shfl_xor_sync(0xffffffff, ps0, 1);
        ps0 += __shfl_xor_sync(0xffffffff, ps0, 2);
        ps1 += __shfl_xor_sync(0xffffffff, ps1, 1);
        ps1 += __shfl_xor_sync(0xffffffff, ps1, 2);

        l0 = l0 * sc0 + ps0;  m0 = nm0;
        l1 = l1 * sc1 + ps1;  m1 = nm1;

        #pragma unroll
        for (int nt = 0; nt < 8; nt++) {
            oacc[nt].x *= sc0;  oacc[nt].y *= sc0;
            oacc[nt].z *= sc1;  oacc[nt].w *= sc1;
        }

        #pragma unroll
        for (int ks = 0; ks < 8; ks++) {
            float x0 = __shfl_sync(0xffffffff, sa[ks].x, lq0);
            float y0 = __shfl_sync(0xffffffff, sa[ks].y, lq0);
            float z0 = __shfl_sync(0xffffffff, sa[ks].z, lq0);
            float w0 = __shfl_sync(0xffffffff, sa[ks].w, lq0);
            float x1 = __shfl_sync(0xffffffff, sa[ks].x, lq1);
            float y1 = __shfl_sync(0xffffffff, sa[ks].y, lq1);
            float z1 = __shfl_sync(0xffffffff, sa[ks].z, lq1);
            float w1 = __shfl_sync(0xffffffff, sa[ks].w, lq1);
            uint32_t pa[4];
            pa[0] = __float_as_uint(rtf32((t & 1) ? y0 : x0));
            pa[1] = __float_as_uint(rtf32((t & 1) ? w0 : z0));
            pa[2] = __float_as_uint(rtf32((t & 1) ? y1 : x1));
            pa[3] = __float_as_uint(rtf32((t & 1) ? w1 : z1));

            const int kr0 = (ks*8 + t    ) * LDV + g;
            const int kr1 = (ks*8 + t + 4) * LDV + g;
            #pragma unroll
            for (int nt = 0; nt < 8; nt++) {
                uint32_t b0 = __float_as_uint(Vs[kr0 + nt*8]);
                uint32_t b1 = __float_as_uint(Vs[kr1 + nt*8]);
                mma8(oacc[nt], pa, b0, b1);
            }
        }
        __syncthreads();
    }

    const float inv0 = 1.f / l0;
    const float inv1 = 1.f / l1;
    float* o0 = ao + (long)(b*S_ + R0) * D_ + h*HD_;
    float* o1 = ao + (long)(b*S_ + R1) * D_ + h*HD_;
    #pragma unroll
    for (int nt = 0; nt < 8; nt++) {
        *(float2*)(o0 + nt*8 + 2*t) =
            make_float2(rtf32(oacc[nt].x * inv0), rtf32(oacc[nt].y * inv0));
        *(float2*)(o1 + nt*8 + 2*t) =
            make_float2(rtf32(oacc[nt].z * inv1), rtf32(oacc[nt].w * inv1));
    }
}

// ===========================================================================
extern "C" void kernel_launch(void* const* d_in, const int* in_sizes, int n_in,
                              void* d_out, int out_size)
{
    const float* X    = (const float*)d_in[0];
    const float* Wat  = (const float*)d_in[1];
    const float* bat  = (const float*)d_in[2];
    const float* Sp   = (const float*)d_in[3];
    const float* Wp   = (const float*)d_in[4];
    const float* bp   = (const float*)d_in[5];
    float* out = (float*)d_out;

    float *wf, *bf, *x2, *ao, *xr, *wpr;
    cudaGetSymbolAddress((void**)&wf,  g_wf);
    cudaGetSymbolAddress((void**)&bf,  g_bf);
    cudaGetSymbolAddress((void**)&x2,  g_x2);
    cudaGetSymbolAddress((void**)&ao,  g_ao);
    cudaGetSymbolAddress((void**)&xr,  g_xr);
    cudaGetSymbolAddress((void**)&wpr, g_wpr);

    const int dynSmem = STG * (GBM*LDA + GBK*LDB) * 4;   // 56064 B
    cudaFuncSetAttribute(tf32_gemm_bias,
                         cudaFuncAttributeMaxDynamicSharedMemorySize, dynSmem);

    // 0. prep: tf32-round GEMM operands; fold S_proj (+bias in extra block)
    round_prep<<<(M_*D_ + D_*D_ + 255)/256, 256>>>(X, Wp, xr, wpr);
    fold_weights<<<D_ + 1, 256>>>(Wat, bat, Sp, wf, bf);

    // 1. folded QKV GEMM
    dim3 g1(NF/GBN, M_/GBM);
    tf32_gemm_bias<<<g1, 256, dynSmem>>>(xr, wf, bf, x2, M_, NF, D_);

    // 2. causal flash attention
    dim3 g3(S_/64, H_, B_);
    attn_mma<<<g3, 128>>>(x2, ao);

    // 3. output projection GEMM
    dim3 g4(D_/GBN, M_/GBM);
    tf32_gemm_bias<<<g4, 256, dynSmem>>>(ao, wpr, bp, out, M_, D_, D_);
}

// round 7
// speedup vs baseline: 1.6175x; 1.0027x over previous
#include <cuda_runtime.h>
#include <mma.h>
#include <math.h>
#include <stdint.h>

using namespace nvcuda;

#define B_   2
#define S_   2048
#define D_   1024
#define H_   16
#define HD_  64
#define KJL  32
#define M_   (B_*S_)
#define NF   2048         // folded qkv width: 512 qjl | 512 kjl | 1024 v

// ---- scratch (device globals: allocation is forbidden) --------------------
__device__ float g_wf[D_*NF];     // folded weights (tf32-rounded)
__device__ float g_bf[NF];        // folded bias (fp32)
__device__ float g_x2[M_*NF];     // folded qkv output
__device__ float g_ao[M_*D_];     // attention output (tf32-rounded)
__device__ float g_xr[M_*D_];     // tf32-rounded input X
__device__ float g_wpr[D_*D_];    // tf32-rounded W_proj

__device__ __forceinline__ float rtf32(float x) {
    asm("cvt.rna.tf32.f32 %0, %1;" : "=f"(x) : "f"(x));
    return x;
}
__device__ __forceinline__ void cpa16(uint32_t dst, const void* src) {
    asm volatile("cp.async.cg.shared.global [%0], [%1], 16;" :: "r"(dst), "l"(src));
}
__device__ __forceinline__ void cp_commit() {
    asm volatile("cp.async.commit_group;");
}
template<int N> __device__ __forceinline__ void cp_wait() {
    asm volatile("cp.async.wait_group %0;" :: "n"(N));
}

// ===========================================================================
// Prep: tf32-round X and W_proj in one launch
// ===========================================================================
__global__ void round_prep(const float* __restrict__ X, const float* __restrict__ Wp,
                           float* __restrict__ xr, float* __restrict__ wpr)
{
    int i = blockIdx.x * 256 + threadIdx.x;
    if (i < M_*D_) xr[i] = rtf32(X[i]);
    else {
        int j = i - M_*D_;
        if (j < D_*D_) wpr[j] = rtf32(Wp[j]);
    }
}

// ===========================================================================
// Fold S_proj into attention weights (tf32-rounded) + bias (block D_)
// ===========================================================================
__global__ __launch_bounds__(256)
void fold_weights(const float* __restrict__ Wat, const float* __restrict__ bat,
                  const float* __restrict__ Sp,
                  float* __restrict__ Wf, float* __restrict__ bf)
{
    const int tid = threadIdx.x;

    if (blockIdx.x == D_) {               // bias block
        for (int i = tid; i < NF; i += 256) {
            if (i < 1024) {
                const int part = i >> 9, hk = i & 511, h = hk >> 5, k = hk & 31;
                float a = 0.f;
                #pragma unroll
                for (int e = 0; e < HD_; e++)
                    a += bat[part*1024 + h*HD_ + e] * Sp[k*HD_ + e];
                bf[i] = a;
            } else {
                bf[i] = bat[2048 + (i - 1024)];
            }
        }
        return;
    }

    __shared__ float w[2048];
    __shared__ float sp[KJL][HD_];
    const int d = blockIdx.x;
    for (int i = tid; i < 2048; i += 256) w[i] = Wat[(long)d * (3*D_) + i];
    for (int i = tid; i < KJL*HD_; i += 256) sp[i >> 6][i & 63] = Sp[i];
    __syncthreads();

    for (int o = tid; o < 1024; o += 256) {
        const int part = o >> 9;
        const int hk = o & 511, h = hk >> 5, k = hk & 31;
        const float* src = w + part * 1024 + h * HD_;
        float a = 0.f;
        #pragma unroll
        for (int e = 0; e < HD_; e++) a += src[e] * sp[k][e];
        Wf[(long)d * NF + part * 512 + hk] = rtf32(a);
    }
    for (int i = tid; i < 1024; i += 256)
        Wf[(long)d * NF + 1024 + i] = rtf32(Wat[(long)d * (3*D_) + 2048 + i]);
}

// ===========================================================================
// TF32 tensor-core GEMM + bias. Operands pre-rounded to tf32 in gmem.
// 128x128x16 block tile, 128 thr = 4 warps (2m x 2n), warp tile 64x64
// (4x4 wmma frags -> 16 mma per 8 fragment loads). 3-stage cp.async.
// ===========================================================================
#define GBM 128
#define GBN 128
#define GBK 16
#define LDA 20
#define LDB 132
#define STG 3
#define ASTAGE (GBM*LDA*4)
#define BSTAGE (GBK*LDB*4)

__global__ __launch_bounds__(128, 2)
void tf32_gemm_bias(const float* __restrict__ A, const float* __restrict__ Bm,
                    const float* __restrict__ bias, float* __restrict__ C,
                    int M, int N, int K)
{
    extern __shared__ float dyn[];
    float* As = dyn;                        // [STG][GBM][LDA]
    float* Bs = dyn + STG*GBM*LDA;          // [STG][GBK][LDB]
    __shared__ float biasS[16][LDB];

    const int tid  = threadIdx.x;
    const int wid  = tid >> 5;
    const int brow = blockIdx.y * GBM;
    const int bcol = blockIdx.x * GBN;
    const int wm   = (wid & 1) * 64;
    const int wn   = (wid >> 1) * 64;

    #pragma unroll
    for (int t = 0; t < 16; t++) {
        int idx = tid + t * 128;
        biasS[idx >> 7][idx & 127] = bias[bcol + (idx & 127)];
    }
    __syncthreads();

    wmma::fragment<wmma::accumulator, 16, 16, 8, float> acc[4][4];
    #pragma unroll
    for (int i = 0; i < 4; i++)
        #pragma unroll
        for (int j = 0; j < 4; j++)
            wmma::load_matrix_sync(acc[i][j], &biasS[0][wn + j*16], LDB,
                                   wmma::mem_row_major);

    const int ar0 = tid >> 2,  ac0 = (tid & 3) << 2;   // A: 32 rows/pass, 4 passes
    const int br0 = tid >> 5,  bc0 = (tid & 31) << 2;  // B: 4 rows/pass, 4 passes

    const float* ApG = A  + (long)(brow + ar0) * K + ac0;
    const float* BpG = Bm + (long)br0 * N + bcol + bc0;

    const uint32_t sAs = (uint32_t)__cvta_generic_to_shared(As);
    const uint32_t sBs = (uint32_t)__cvta_generic_to_shared(Bs);
    const uint32_t aoff = (ar0 * LDA + ac0) * 4;
    const uint32_t boff = (br0 * LDB + bc0) * 4;

    const int KC = K / GBK;
    int fetch = 0;

    #pragma unroll
    for (int p = 0; p < STG - 1; p++) {
        uint32_t da = sAs + p * ASTAGE + aoff;
        uint32_t db = sBs + p * BSTAGE + boff;
        #pragma unroll
        for (int i = 0; i < 4; i++) {
            cpa16(da + i*(32*LDA*4), ApG + (long)i*32*K + fetch*GBK);
            cpa16(db + i*(4*LDB*4),  BpG + (long)(fetch*GBK + i*4) * N);
        }
        cp_commit();
        fetch++;
    }

    int s = 0;
    for (int c = 0; c < KC; c++) {
        cp_wait<STG - 2>();
        __syncthreads();

        const float* Asb = As + s * GBM * LDA;
        const float* Bsb = Bs + s * GBK * LDB;

        #pragma unroll
        for (int kk = 0; kk < GBK; kk += 8) {
            wmma::fragment<wmma::matrix_a, 16, 16, 8, wmma::precision::tf32,
                           wmma::row_major> a_frag[4];
            wmma::fragment<wmma::matrix_b, 16, 16, 8, wmma::precision::tf32,
                           wmma::row_major> b_frag[4];
            #pragma unroll
            for (int i = 0; i < 4; i++)
                wmma::load_matrix_sync(a_frag[i], Asb + (wm + i*16)*LDA + kk, LDA);
            #pragma unroll
            for (int j = 0; j < 4; j++)
                wmma::load_matrix_sync(b_frag[j], Bsb + kk*LDB + wn + j*16, LDB);
            #pragma unroll
            for (int i = 0; i < 4; i++)
                #pragma unroll
                for (int j = 0; j < 4; j++)
                    wmma::mma_sync(acc[i][j], a_frag[i], b_frag[j], acc[i][j]);
        }

        if (fetch < KC) {
            const int p = (s + STG - 1) >= STG ? s - 1 : s + STG - 1;  // (c+STG-1)%STG
            uint32_t da = sAs + p * ASTAGE + aoff;
            uint32_t db = sBs + p * BSTAGE + boff;
            #pragma unroll
            for (int i = 0; i < 4; i++) {
                cpa16(da + i*(32*LDA*4), ApG + (long)i*32*K + fetch*GBK);
                cpa16(db + i*(4*LDB*4),  BpG + (long)(fetch*GBK + i*4) * N);
            }
            fetch++;
        }
        cp_commit();
        s = (s + 1 == STG) ? 0 : s + 1;
    }

    #pragma unroll
    for (int i = 0; i < 4; i++)
        #pragma unroll
        for (int j = 0; j < 4; j++)
            wmma::store_matrix_sync(
                C + (long)(brow + wm + i*16) * N + bcol + wn + j*16,
                acc[i][j], N, wmma::mem_row_major);
}

// ===========================================================================
// Tensor-core causal flash attention (m16n8k8 tf32), shuffle-based P reshape.
// 256 thr = 8 warps, 128 queries/block (warp w owns rows w*16..w*16+15).
// 64-key tiles; fully-masked tiles skipped per warp. Heavy q-tiles first.
// grid = (S/128, H, B)
// ===========================================================================
#define LDK 36
#define LDV 68

__device__ __forceinline__ void mma8(float4& d, const uint32_t* a,
                                     uint32_t b0, uint32_t b1)
{
    asm volatile(
        "mma.sync.aligned.m16n8k8.row.col.f32.tf32.tf32.f32 "
        "{%0,%1,%2,%3},{%4,%5,%6,%7},{%8,%9},{%0,%1,%2,%3};"
        : "+f"(d.x), "+f"(d.y), "+f"(d.z), "+f"(d.w)
        : "r"(a[0]), "r"(a[1]), "r"(a[2]), "r"(a[3]), "r"(b0), "r"(b1));
}

__global__ __launch_bounds__(256)
void attn_mma(const float* __restrict__ x2, float* __restrict__ ao)
{
    __shared__ float Ks[64 * LDK];
    __shared__ float Vs[64 * LDV];     // also Q staging ([128][32] = 4096 <= 4352)

    const int tid  = threadIdx.x;
    const int w    = tid >> 5;
    const int lane = tid & 31;
    const int g    = lane >> 2;
    const int t    = lane & 3;
    const int h    = blockIdx.y;
    const int b    = blockIdx.z;
    const int qt   = gridDim.x - 1 - blockIdx.x;   // heavy tiles first
    const int q0   = qt * 128;

    // ---- stage Q [128][32] (tf32-rounded) into Vs -------------------------
    {
        const float* qb = x2 + (long)(b * S_ + q0) * NF + h * KJL;
        #pragma unroll
        for (int i = 0; i < 4; i++) {
            int idx = tid + i * 256;
            int r = idx >> 3, c = (idx & 7) << 2;
            float4 v = *(const float4*)(qb + (long)r * NF + c);
            Vs[r*32 + c + 0] = rtf32(v.x);
            Vs[r*32 + c + 1] = rtf32(v.y);
            Vs[r*32 + c + 2] = rtf32(v.z);
            Vs[r*32 + c + 3] = rtf32(v.w);
        }
    }
    __syncthreads();

    uint32_t qf[4][4];
    #pragma unroll
    for (int ks = 0; ks < 4; ks++) {
        qf[ks][0] = __float_as_uint(Vs[(w*16 + g    )*32 + ks*8 + t    ]);
        qf[ks][1] = __float_as_uint(Vs[(w*16 + g + 8)*32 + ks*8 + t    ]);
        qf[ks][2] = __float_as_uint(Vs[(w*16 + g    )*32 + ks*8 + t + 4]);
        qf[ks][3] = __float_as_uint(Vs[(w*16 + g + 8)*32 + ks*8 + t + 4]);
    }
    __syncthreads();

    float4 oacc[8];
    #pragma unroll
    for (int nt = 0; nt < 8; nt++) oacc[nt] = make_float4(0.f, 0.f, 0.f, 0.f);
    float m0 = -1e30f, m1 = -1e30f, l0 = 0.f, l1 = 0.f;

    const int R0 = q0 + w*16 + g;
    const int R1 = R0 + 8;
    const int Rmax = q0 + w*16 + 15;
    const int nkt = 2*qt + 2;
    const int lq0 = (lane & ~3) | (t >> 1);
    const int lq1 = lq0 + 2;

    for (int kt = 0; kt < nkt; kt++) {
        {
            const float* kb = x2 + (long)(b*S_ + kt*64) * NF + 512 + h*KJL;
            #pragma unroll
            for (int i = 0; i < 2; i++) {
                int idx = tid + i * 256;
                int r = idx >> 3, c = (idx & 7) << 2;
                float4 v = *(const float4*)(kb + (long)r * NF + c);
                Ks[r*LDK + c + 0] = rtf32(v.x);
                Ks[r*LDK + c + 1] = rtf32(v.y);
                Ks[r*LDK + c + 2] = rtf32(v.z);
                Ks[r*LDK + c + 3] = rtf32(v.w);
            }
            const float* vb = x2 + (long)(b*S_ + kt*64) * NF + 1024 + h*HD_;
            #pragma unroll
            for (int i = 0; i < 4; i++) {
                int idx = tid + i * 256;
                int r = idx >> 4, c = (idx & 15) << 2;
                float4 v = *(const float4*)(vb + (long)r * NF + c);
                Vs[r*LDV + c + 0] = rtf32(v.x);
                Vs[r*LDV + c + 1] = rtf32(v.y);
                Vs[r*LDV + c + 2] = rtf32(v.z);
                Vs[r*LDV + c + 3] = rtf32(v.w);
            }
        }
        __syncthreads();

        if (kt*64 <= Rmax) {
            float4 sa[8];
            #pragma unroll
            for (int nt = 0; nt < 8; nt++) {
                sa[nt] = make_float4(0.f, 0.f, 0.f, 0.f);
                #pragma unroll
                for (int ks = 0; ks < 4; ks++) {
                    uint32_t b0 = __float_as_uint(Ks[(nt*8 + g)*LDK + ks*8 + t    ]);
                    uint32_t b1 = __float_as_uint(Ks[(nt*8 + g)*LDK + ks*8 + t + 4]);
                    mma8(sa[nt], qf[ks], b0, b1);
                }
            }

            float mx0 = -1e30f, mx1 = -1e30f;
            #pragma unroll
            for (int nt = 0; nt < 8; nt++) {
                const int c0 = kt*64 + nt*8 + 2*t;
                const int c1 = c0 + 1;
                sa[nt].x = (c0 <= R0) ? sa[nt].x * 0.125f : -1e30f;
                sa[nt].y = (c1 <= R0) ? sa[nt].y * 0.125f : -1e30f;
                sa[nt].z = (c0 <= R1) ? sa[nt].z * 0.125f : -1e30f;
                sa[nt].w = (c1 <= R1) ? sa[nt].w * 0.125f : -1e30f;
                mx0 = fmaxf(mx0, fmaxf(sa[nt].x, sa[nt].y));
                mx1 = fmaxf(mx1, fmaxf(sa[nt].z, sa[nt].w));
            }
            mx0 = fmaxf(mx0, __shfl_xor_sync(0xffffffff, mx0, 1));
            mx0 = fmaxf(mx0, __shfl_xor_sync(0xffffffff, mx0, 2));
            mx1 = fmaxf(mx1, __shfl_xor_sync(0xffffffff, mx1, 1));
            mx1 = fmaxf(mx1, __shfl_xor_sync(0xffffffff, mx1, 2));

            const float nm0 = fmaxf(m0, mx0);
            const float nm1 = fmaxf(m1, mx1);
            const float sc0 = __expf(m0 - nm0);
            const float sc1 = __expf(m1 - nm1);

            float ps0 = 0.f, ps1 = 0.f;
            #pragma unroll
            for (int nt = 0; nt < 8; nt++) {
                sa[nt].x = __expf(sa[nt].x - nm0);
                sa[nt].y = __expf(sa[nt].y - nm0);
                sa[nt].z = __expf(sa[nt].z - nm1);
                sa[nt].w = __expf(sa[nt].w - nm1);
                ps0 += sa[nt].x + sa[nt].y;
                ps1 += sa[nt].z + sa[nt].w;
            }
            ps0 += __shfl_xor_sync(0xffffffff, ps0, 1);
            ps0 += __shfl_xor_sync(0xffffffff, ps0, 2);
            ps1 += __shfl_xor_sync(0xffffffff, ps1, 1);
            ps1 += __shfl_xor_sync(0xffffffff, ps1, 2);

            l0 = l0 * sc0 + ps0;  m0 = nm0;
            l1 = l1 * sc1 + ps1;  m1 = nm1;

            #pragma unroll
            for (int nt = 0; nt < 8; nt++) {
                oacc[nt].x *= sc0;  oacc[nt].y *= sc0;
                oacc[nt].z *= sc1;  oacc[nt].w *= sc1;
            }

            #pragma unroll
            for (int ks = 0; ks < 8; ks++) {
                float x0 = __shfl_sync(0xffffffff, sa[ks].x, lq0);
                float y0 = __shfl_sync(0xffffffff, sa[ks].y, lq0);
                float z0 = __shfl_sync(0xffffffff, sa[ks].z, lq0);
                float w0 = __shfl_sync(0xffffffff, sa[ks].w, lq0);
                float x1 = __shfl_sync(0xffffffff, sa[ks].x, lq1);
                float y1 = __shfl_sync(0xffffffff, sa[ks].y, lq1);
                float z1 = __shfl_sync(0xffffffff, sa[ks].z, lq1);
                float w1 = __shfl_sync(0xffffffff, sa[ks].w, lq1);
                uint32_t pa[4];
                pa[0] = __float_as_uint(rtf32((t & 1) ? y0 : x0));
                pa[1] = __float_as_uint(rtf32((t & 1) ? w0 : z0));
                pa[2] = __float_as_uint(rtf32((t & 1) ? y1 : x1));
                pa[3] = __float_as_uint(rtf32((t & 1) ? w1 : z1));

                const int kr0 = (ks*8 + t    ) * LDV + g;
                const int kr1 = (ks*8 + t + 4) * LDV + g;
                #pragma unroll
                for (int nt = 0; nt < 8; nt++) {
                    uint32_t b0 = __float_as_uint(Vs[kr0 + nt*8]);
                    uint32_t b1 = __float_as_uint(Vs[kr1 + nt*8]);
                    mma8(oacc[nt], pa, b0, b1);
                }
            }
        }
        __syncthreads();
    }

    const float inv0 = 1.f / l0;
    const float inv1 = 1.f / l1;
    float* o0 = ao + (long)(b*S_ + R0) * D_ + h*HD_;
    float* o1 = ao + (long)(b*S_ + R1) * D_ + h*HD_;
    #pragma unroll
    for (int nt = 0; nt < 8; nt++) {
        *(float2*)(o0 + nt*8 + 2*t) =
            make_float2(rtf32(oacc[nt].x * inv0), rtf32(oacc[nt].y * inv0));
        *(float2*)(o1 + nt*8 + 2*t) =
            make_float2(rtf32(oacc[nt].z * inv1), rtf32(oacc[nt].w * inv1));
    }
}

// ===========================================================================
extern "C" void kernel_launch(void* const* d_in, const int* in_sizes, int n_in,
                              void* d_out, int out_size)
{
    const float* X    = (const float*)d_in[0];
    const float* Wat  = (const float*)d_in[1];
    const float* bat  = (const float*)d_in[2];
    const float* Sp   = (const float*)d_in[3];
    const float* Wp   = (const float*)d_in[4];
    const float* bp   = (const float*)d_in[5];
    float* out = (float*)d_out;

    float *wf, *bf, *x2, *ao, *xr, *wpr;
    cudaGetSymbolAddress((void**)&wf,  g_wf);
    cudaGetSymbolAddress((void**)&bf,  g_bf);
    cudaGetSymbolAddress((void**)&x2,  g_x2);
    cudaGetSymbolAddress((void**)&ao,  g_ao);
    cudaGetSymbolAddress((void**)&xr,  g_xr);
    cudaGetSymbolAddress((void**)&wpr, g_wpr);

    const int dynSmem = STG * (GBM*LDA + GBK*LDB) * 4;   // 56064 B
    cudaFuncSetAttribute(tf32_gemm_bias,
                         cudaFuncAttributeMaxDynamicSharedMemorySize, dynSmem);

    // 0. prep: tf32-round GEMM operands; fold S_proj (+bias in extra block)
    round_prep<<<(M_*D_ + D_*D_ + 255)/256, 256>>>(X, Wp, xr, wpr);
    fold_weights<<<D_ + 1, 256>>>(Wat, bat, Sp, wf, bf);

    // 1. folded QKV GEMM
    dim3 g1(NF/GBN, M_/GBM);
    tf32_gemm_bias<<<g1, 128, dynSmem>>>(xr, wf, bf, x2, M_, NF, D_);

    // 2. causal flash attention
    dim3 g3(S_/128, H_, B_);
    attn_mma<<<g3, 256>>>(x2, ao);

    // 3. output projection GEMM
    dim3 g4(D_/GBN, M_/GBM);
    tf32_gemm_bias<<<g4, 128, dynSmem>>>(ao, wpr, bp, out, M_, D_, D_);
}

// round 9
// speedup vs baseline: 1.6893x; 1.0444x over previous
#include <cuda_runtime.h>
#include <mma.h>
#include <math.h>
#include <stdint.h>

using namespace nvcuda;

#define B_   2
#define S_   2048
#define D_   1024
#define H_   16
#define HD_  64
#define KJL  32
#define M_   (B_*S_)
#define NF   2048         // folded qkv width: 512 qjl | 512 kjl | 1024 v

// ---- scratch (device globals: allocation is forbidden) --------------------
__device__ float g_wf[D_*NF];     // folded weights (tf32-rounded)
__device__ float g_bf[NF];        // folded bias (fp32)
__device__ float g_x2[M_*NF];     // folded qkv output (tf32-rounded by epilogue)
__device__ float g_ao[M_*D_];     // attention output (tf32-rounded)
__device__ float g_xr[M_*D_];     // tf32-rounded input X
__device__ float g_wpr[D_*D_];    // tf32-rounded W_proj

__device__ __forceinline__ float rtf32(float x) {
    asm("cvt.rna.tf32.f32 %0, %1;" : "=f"(x) : "f"(x));
    return x;
}
__device__ __forceinline__ void cpa16(uint32_t dst, const void* src) {
    asm volatile("cp.async.cg.shared.global [%0], [%1], 16;" :: "r"(dst), "l"(src));
}
__device__ __forceinline__ void cp_commit() {
    asm volatile("cp.async.commit_group;");
}
template<int N> __device__ __forceinline__ void cp_wait() {
    asm volatile("cp.async.wait_group %0;" :: "n"(N));
}

// ===========================================================================
// Prep: tf32-round X and W_proj in one launch
// ===========================================================================
__global__ void round_prep(const float* __restrict__ X, const float* __restrict__ Wp,
                           float* __restrict__ xr, float* __restrict__ wpr)
{
    int i = blockIdx.x * 256 + threadIdx.x;
    if (i < M_*D_) xr[i] = rtf32(X[i]);
    else {
        int j = i - M_*D_;
        if (j < D_*D_) wpr[j] = rtf32(Wp[j]);
    }
}

// ===========================================================================
// Fold S_proj into attention weights (tf32-rounded) + bias (block D_)
// ===========================================================================
__global__ __launch_bounds__(256)
void fold_weights(const float* __restrict__ Wat, const float* __restrict__ bat,
                  const float* __restrict__ Sp,
                  float* __restrict__ Wf, float* __restrict__ bf)
{
    const int tid = threadIdx.x;

    if (blockIdx.x == D_) {               // bias block
        for (int i = tid; i < NF; i += 256) {
            if (i < 1024) {
                const int part = i >> 9, hk = i & 511, h = hk >> 5, k = hk & 31;
                float a = 0.f;
                #pragma unroll
                for (int e = 0; e < HD_; e++)
                    a += bat[part*1024 + h*HD_ + e] * Sp[k*HD_ + e];
                bf[i] = a;
            } else {
                bf[i] = bat[2048 + (i - 1024)];
            }
        }
        return;
    }

    __shared__ float w[2048];
    __shared__ float sp[KJL][HD_];
    const int d = blockIdx.x;
    for (int i = tid; i < 2048; i += 256) w[i] = Wat[(long)d * (3*D_) + i];
    for (int i = tid; i < KJL*HD_; i += 256) sp[i >> 6][i & 63] = Sp[i];
    __syncthreads();

    for (int o = tid; o < 1024; o += 256) {
        const int part = o >> 9;
        const int hk = o & 511, h = hk >> 5, k = hk & 31;
        const float* src = w + part * 1024 + h * HD_;
        float a = 0.f;
        #pragma unroll
        for (int e = 0; e < HD_; e++) a += src[e] * sp[k][e];
        Wf[(long)d * NF + part * 512 + hk] = rtf32(a);
    }
    for (int i = tid; i < 1024; i += 256)
        Wf[(long)d * NF + 1024 + i] = rtf32(Wat[(long)d * (3*D_) + 2048 + i]);
}

// ===========================================================================
// TF32 tensor-core GEMM + bias. Operands pre-rounded to tf32 in gmem.
// 128x128x16 block tile, 128 thr = 4 warps (2m x 2n), warp tile 64x64.
// 3-stage cp.async. Optional tf32 rounding of C in epilogue (roundC).
// ===========================================================================
#define GBM 128
#define GBN 128
#define GBK 16
#define LDA 20
#define LDB 132
#define STG 3
#define ASTAGE (GBM*LDA*4)
#define BSTAGE (GBK*LDB*4)

__global__ __launch_bounds__(128, 2)
void tf32_gemm_bias(const float* __restrict__ A, const float* __restrict__ Bm,
                    const float* __restrict__ bias, float* __restrict__ C,
                    int M, int N, int K, int roundC)
{
    extern __shared__ float dyn[];
    float* As = dyn;                        // [STG][GBM][LDA]
    float* Bs = dyn + STG*GBM*LDA;          // [STG][GBK][LDB]
    __shared__ float biasS[16][LDB];

    const int tid  = threadIdx.x;
    const int wid  = tid >> 5;
    const int brow = blockIdx.y * GBM;
    const int bcol = blockIdx.x * GBN;
    const int wm   = (wid & 1) * 64;
    const int wn   = (wid >> 1) * 64;

    #pragma unroll
    for (int t = 0; t < 16; t++) {
        int idx = tid + t * 128;
        biasS[idx >> 7][idx & 127] = bias[bcol + (idx & 127)];
    }
    __syncthreads();

    wmma::fragment<wmma::accumulator, 16, 16, 8, float> acc[4][4];
    #pragma unroll
    for (int i = 0; i < 4; i++)
        #pragma unroll
        for (int j = 0; j < 4; j++)
            wmma::load_matrix_sync(acc[i][j], &biasS[0][wn + j*16], LDB,
                                   wmma::mem_row_major);

    const int ar0 = tid >> 2,  ac0 = (tid & 3) << 2;
    const int br0 = tid >> 5,  bc0 = (tid & 31) << 2;

    const float* ApG = A  + (long)(brow + ar0) * K + ac0;
    const float* BpG = Bm + (long)br0 * N + bcol + bc0;

    const uint32_t sAs = (uint32_t)__cvta_generic_to_shared(As);
    const uint32_t sBs = (uint32_t)__cvta_generic_to_shared(Bs);
    const uint32_t aoff = (ar0 * LDA + ac0) * 4;
    const uint32_t boff = (br0 * LDB + bc0) * 4;

    const int KC = K / GBK;
    int fetch = 0;

    #pragma unroll
    for (int p = 0; p < STG - 1; p++) {
        uint32_t da = sAs + p * ASTAGE + aoff;
        uint32_t db = sBs + p * BSTAGE + boff;
        #pragma unroll
        for (int i = 0; i < 4; i++) {
            cpa16(da + i*(32*LDA*4), ApG + (long)i*32*K + fetch*GBK);
            cpa16(db + i*(4*LDB*4),  BpG + (long)(fetch*GBK + i*4) * N);
        }
        cp_commit();
        fetch++;
    }

    int s = 0;
    for (int c = 0; c < KC; c++) {
        cp_wait<STG - 2>();
        __syncthreads();

        const float* Asb = As + s * GBM * LDA;
        const float* Bsb = Bs + s * GBK * LDB;

        #pragma unroll
        for (int kk = 0; kk < GBK; kk += 8) {
            wmma::fragment<wmma::matrix_a, 16, 16, 8, wmma::precision::tf32,
                           wmma::row_major> a_frag[4];
            wmma::fragment<wmma::matrix_b, 16, 16, 8, wmma::precision::tf32,
                           wmma::row_major> b_frag[4];
            #pragma unroll
            for (int i = 0; i < 4; i++)
                wmma::load_matrix_sync(a_frag[i], Asb + (wm + i*16)*LDA + kk, LDA);
            #pragma unroll
            for (int j = 0; j < 4; j++)
                wmma::load_matrix_sync(b_frag[j], Bsb + kk*LDB + wn + j*16, LDB);
            #pragma unroll
            for (int i = 0; i < 4; i++)
                #pragma unroll
                for (int j = 0; j < 4; j++)
                    wmma::mma_sync(acc[i][j], a_frag[i], b_frag[j], acc[i][j]);
        }

        if (fetch < KC) {
            const int p = (s + STG - 1) >= STG ? s - 1 : s + STG - 1;  // (c+STG-1)%STG
            uint32_t da = sAs + p * ASTAGE + aoff;
            uint32_t db = sBs + p * BSTAGE + boff;
            #pragma unroll
            for (int i = 0; i < 4; i++) {
                cpa16(da + i*(32*LDA*4), ApG + (long)i*32*K + fetch*GBK);
                cpa16(db + i*(4*LDB*4),  BpG + (long)(fetch*GBK + i*4) * N);
            }
            fetch++;
        }
        cp_commit();
        s = (s + 1 == STG) ? 0 : s + 1;
    }

    if (roundC) {
        #pragma unroll
        for (int i = 0; i < 4; i++)
            #pragma unroll
            for (int j = 0; j < 4; j++)
                #pragma unroll
                for (int e = 0; e < acc[i][j].num_elements; e++)
                    acc[i][j].x[e] = rtf32(acc[i][j].x[e]);
    }

    #pragma unroll
    for (int i = 0; i < 4; i++)
        #pragma unroll
        for (int j = 0; j < 4; j++)
            wmma::store_matrix_sync(
                C + (long)(brow + wm + i*16) * N + bcol + wn + j*16,
                acc[i][j], N, wmma::mem_row_major);
}

// ===========================================================================
// Tensor-core causal flash attention (m16n8k8 tf32). x2 is pre-rounded tf32,
// so K/V tiles stream in via double-buffered cp.async (no conversion work).
// 128 thr = 4 warps, 64 queries/block; Q fragments loaded from gmem.
// grid = (S/64, H, B), heavy q-tiles first. 4 blocks/SM (RF- and smem-exact).
// ===========================================================================
#define LDK 36
#define LDV 68
#define KBYTES (64*LDK*4)
#define VBYTES (64*LDV*4)

__device__ __forceinline__ void mma8(float4& d, const uint32_t* a,
                                     uint32_t b0, uint32_t b1)
{
    asm volatile(
        "mma.sync.aligned.m16n8k8.row.col.f32.tf32.tf32.f32 "
        "{%0,%1,%2,%3},{%4,%5,%6,%7},{%8,%9},{%0,%1,%2,%3};"
        : "+f"(d.x), "+f"(d.y), "+f"(d.z), "+f"(d.w)
        : "r"(a[0]), "r"(a[1]), "r"(a[2]), "r"(a[3]), "r"(b0), "r"(b1));
}

__global__ __launch_bounds__(128, 4)
void attn_mma(const float* __restrict__ x2, float* __restrict__ ao)
{
    extern __shared__ float smem[];
    float* Ks = smem;                 // [2][64*LDK]
    float* Vs = smem + 2*64*LDK;      // [2][64*LDV]

    const int tid  = threadIdx.x;
    const int w    = tid >> 5;
    const int lane = tid & 31;
    const int g    = lane >> 2;
    const int t    = lane & 3;
    const int h    = blockIdx.y;
    const int b    = blockIdx.z;
    const int qt   = gridDim.x - 1 - blockIdx.x;   // heavy tiles first
    const int q0   = qt * 64;

    const uint32_t sK = (uint32_t)__cvta_generic_to_shared(Ks);
    const uint32_t sV = (uint32_t)__cvta_generic_to_shared(Vs);

    // per-thread cp.async offsets
    const int kr = tid >> 3, kc = (tid & 7) << 2;    // K: +16 rows per pass, 4 passes
    const int vr = tid >> 4, vc = (tid & 15) << 2;   // V: +8 rows per pass, 8 passes
    const float* kbase = x2 + (long)(b*S_) * NF + 512  + h*KJL;
    const float* vbase = x2 + (long)(b*S_) * NF + 1024 + h*HD_;

    #define LOAD_TILE(kt_, bb_)                                                 \
    {                                                                           \
        const float* kb = kbase + (long)((kt_)*64 + kr) * NF + kc;              \
        const float* vb = vbase + (long)((kt_)*64 + vr) * NF + vc;              \
        uint32_t dk = sK + (bb_)*KBYTES + (kr*LDK + kc)*4;                      \
        uint32_t dv = sV + (bb_)*VBYTES + (vr*LDV + vc)*4;                      \
        _Pragma("unroll")                                                       \
        for (int i_ = 0; i_ < 4; i_++)                                          \
            cpa16(dk + i_*(16*LDK*4), kb + (long)i_*16*NF);                     \
        _Pragma("unroll")                                                       \
        for (int i_ = 0; i_ < 8; i_++)                                          \
            cpa16(dv + i_*(8*LDV*4),  vb + (long)i_*8*NF);                      \
    }

    // ---- Q fragments straight from gmem (already tf32) --------------------
    uint32_t qf[4][4];
    {
        const float* qb = x2 + (long)(b*S_ + q0) * NF + h*KJL;
        #pragma unroll
        for (int ks = 0; ks < 4; ks++) {
            qf[ks][0] = __float_as_uint(qb[(long)(w*16 + g    )*NF + ks*8 + t    ]);
            qf[ks][1] = __float_as_uint(qb[(long)(w*16 + g + 8)*NF + ks*8 + t    ]);
            qf[ks][2] = __float_as_uint(qb[(long)(w*16 + g    )*NF + ks*8 + t + 4]);
            qf[ks][3] = __float_as_uint(qb[(long)(w*16 + g + 8)*NF + ks*8 + t + 4]);
        }
    }

    float4 oacc[8];
    #pragma unroll
    for (int nt = 0; nt < 8; nt++) oacc[nt] = make_float4(0.f, 0.f, 0.f, 0.f);
    float m0 = -1e30f, m1 = -1e30f, l0 = 0.f, l1 = 0.f;

    const int R0 = q0 + w*16 + g;
    const int R1 = R0 + 8;
    const int nkt = qt + 1;
    const int lq0 = (lane & ~3) | (t >> 1);
    const int lq1 = lq0 + 2;

    LOAD_TILE(0, 0);
    cp_commit();

    int buf = 0;
    for (int kt = 0; kt < nkt; kt++) {
        if (kt + 1 < nkt) {
            LOAD_TILE(kt + 1, buf ^ 1);
            cp_commit();
            cp_wait<1>();
        } else {
            cp_wait<0>();
        }
        __syncthreads();

        const float* Kb = Ks + buf * (64*LDK);
        const float* Vb = Vs + buf * (64*LDV);

        // ---- S = Q @ K^T ---------------------------------------------------
        float4 sa[8];
        #pragma unroll
        for (int nt = 0; nt < 8; nt++) {
            sa[nt] = make_float4(0.f, 0.f, 0.f, 0.f);
            #pragma unroll
            for (int ks = 0; ks < 4; ks++) {
                uint32_t b0 = __float_as_uint(Kb[(nt*8 + g)*LDK + ks*8 + t    ]);
                uint32_t b1 = __float_as_uint(Kb[(nt*8 + g)*LDK + ks*8 + t + 4]);
                mma8(sa[nt], qf[ks], b0, b1);
            }
        }

        // ---- scale + causal mask + online softmax --------------------------
        float mx0 = -1e30f, mx1 = -1e30f;
        #pragma unroll
        for (int nt = 0; nt < 8; nt++) {
            const int c0 = kt*64 + nt*8 + 2*t;
            const int c1 = c0 + 1;
            sa[nt].x = (c0 <= R0) ? sa[nt].x * 0.125f : -1e30f;
            sa[nt].y = (c1 <= R0) ? sa[nt].y * 0.125f : -1e30f;
            sa[nt].z = (c0 <= R1) ? sa[nt].z * 0.125f : -1e30f;
            sa[nt].w = (c1 <= R1) ? sa[nt].w * 0.125f : -1e30f;
            mx0 = fmaxf(mx0, fmaxf(sa[nt].x, sa[nt].y));
            mx1 = fmaxf(mx1, fmaxf(sa[nt].z, sa[nt].w));
        }
        mx0 = fmaxf(mx0, __shfl_xor_sync(0xffffffff, mx0, 1));
        mx0 = fmaxf(mx0, __shfl_xor_sync(0xffffffff, mx0, 2));
        mx1 = fmaxf(mx1, __shfl_xor_sync(0xffffffff, mx1, 1));
        mx1 = fmaxf(mx1, __shfl_xor_sync(0xffffffff, mx1, 2));

        const float nm0 = fmaxf(m0, mx0);
        const float nm1 = fmaxf(m1, mx1);
        const float sc0 = __expf(m0 - nm0);
        const float sc1 = __expf(m1 - nm1);

        float ps0 = 0.f, ps1 = 0.f;
        #pragma unroll
        for (int nt = 0; nt < 8; nt++) {
            sa[nt].x = __expf(sa[nt].x - nm0);
            sa[nt].y = __expf(sa[nt].y - nm0);
            sa[nt].z = __expf(sa[nt].z - nm1);
            sa[nt].w = __expf(sa[nt].w - nm1);
            ps0 += sa[nt].x + sa[nt].y;
            ps1 += sa[nt].z + sa[nt].w;
        }
        ps0 += __shfl_xor_sync(0xffffffff, ps0, 1);
        ps0 += __shfl_xor_sync(0xffffffff, ps0, 2);
        ps1 += __shfl_xor_sync(0xffffffff, ps1, 1);
        ps1 += __shfl_xor_sync(0xffffffff, ps1, 2);

        l0 = l0 * sc0 + ps0;  m0 = nm0;
        l1 = l1 * sc1 + ps1;  m1 = nm1;

        #pragma unroll
        for (int nt = 0; nt < 8; nt++) {
            oacc[nt].x *= sc0;  oacc[nt].y *= sc0;
            oacc[nt].z *= sc1;  oacc[nt].w *= sc1;
        }

        // ---- O += P @ V : shuffle acc layout -> A-frag layout --------------
        #pragma unroll
        for (int ks = 0; ks < 8; ks++) {
            float x0 = __shfl_sync(0xffffffff, sa[ks].x, lq0);
            float y0 = __shfl_sync(0xffffffff, sa[ks].y, lq0);
            float z0 = __shfl_sync(0xffffffff, sa[ks].z, lq0);
            float w0 = __shfl_sync(0xffffffff, sa[ks].w, lq0);
            float x1 = __shfl_sync(0xffffffff, sa[ks].x, lq1);
            float y1 = __shfl_sync(0xffffffff, sa[ks].y, lq1);
            float z1 = __shfl_sync(0xffffffff, sa[ks].z, lq1);
            float w1 = __shfl_sync(0xffffffff, sa[ks].w, lq1);
            uint32_t pa[4];
            pa[0] = __float_as_uint(rtf32((t & 1) ? y0 : x0));
            pa[1] = __float_as_uint(rtf32((t & 1) ? w0 : z0));
            pa[2] = __float_as_uint(rtf32((t & 1) ? y1 : x1));
            pa[3] = __float_as_uint(rtf32((t & 1) ? w1 : z1));

            const int kr0 = (ks*8 + t    ) * LDV + g;
            const int kr1 = (ks*8 + t + 4) * LDV + g;
            #pragma unroll
            for (int nt = 0; nt < 8; nt++) {
                uint32_t b0 = __float_as_uint(Vb[kr0 + nt*8]);
                uint32_t b1 = __float_as_uint(Vb[kr1 + nt*8]);
                mma8(oacc[nt], pa, b0, b1);
            }
        }
        __syncthreads();   // all warps done with buf before it is refilled
        buf ^= 1;
    }

    // ---- normalize + store (tf32-rounded for the following GEMM) ----------
    const float inv0 = 1.f / l0;
    const float inv1 = 1.f / l1;
    float* o0 = ao + (long)(b*S_ + R0) * D_ + h*HD_;
    float* o1 = ao + (long)(b*S_ + R1) * D_ + h*HD_;
    #pragma unroll
    for (int nt = 0; nt < 8; nt++) {
        *(float2*)(o0 + nt*8 + 2*t) =
            make_float2(rtf32(oacc[nt].x * inv0), rtf32(oacc[nt].y * inv0));
        *(float2*)(o1 + nt*8 + 2*t) =
            make_float2(rtf32(oacc[nt].z * inv1), rtf32(oacc[nt].w * inv1));
    }
}

// ===========================================================================
extern "C" void kernel_launch(void* const* d_in, const int* in_sizes, int n_in,
                              void* d_out, int out_size)
{
    const float* X    = (const float*)d_in[0];
    const float* Wat  = (const float*)d_in[1];
    const float* bat  = (const float*)d_in[2];
    const float* Sp   = (const float*)d_in[3];
    const float* Wp   = (const float*)d_in[4];
    const float* bp   = (const float*)d_in[5];
    float* out = (float*)d_out;

    float *wf, *bf, *x2, *ao, *xr, *wpr;
    cudaGetSymbolAddress((void**)&wf,  g_wf);
    cudaGetSymbolAddress((void**)&bf,  g_bf);
    cudaGetSymbolAddress((void**)&x2,  g_x2);
    cudaGetSymbolAddress((void**)&ao,  g_ao);
    cudaGetSymbolAddress((void**)&xr,  g_xr);
    cudaGetSymbolAddress((void**)&wpr, g_wpr);

    const int gemmSmem = STG * (GBM*LDA + GBK*LDB) * 4;       // 56064 B
    const int attnSmem = 2 * (64*LDK + 64*LDV) * 4;           // 53248 B
    cudaFuncSetAttribute(tf32_gemm_bias,
                         cudaFuncAttributeMaxDynamicSharedMemorySize, gemmSmem);
    cudaFuncSetAttribute(attn_mma,
                         cudaFuncAttributeMaxDynamicSharedMemorySize, attnSmem);

    // 0. prep: tf32-round GEMM operands; fold S_proj (+bias in extra block)
    round_prep<<<(M_*D_ + D_*D_ + 255)/256, 256>>>(X, Wp, xr, wpr);
    fold_weights<<<D_ + 1, 256>>>(Wat, bat, Sp, wf, bf);

    // 1. folded QKV GEMM (epilogue rounds x2 to tf32)
    dim3 g1(NF/GBN, M_/GBM);
    tf32_gemm_bias<<<g1, 128, gemmSmem>>>(xr, wf, bf, x2, M_, NF, D_, 1);

    // 2. causal flash attention
    dim3 g3(S_/64, H_, B_);
    attn_mma<<<g3, 128, attnSmem>>>(x2, ao);

    // 3. output projection GEMM (raw fp32 output)
    dim3 g4(D_/GBN, M_/GBM);
    tf32_gemm_bias<<<g4, 128, gemmSmem>>>(ao, wpr, bp, out, M_, D_, D_, 0);
}

// round 10
// speedup vs baseline: 1.8518x; 1.0962x over previous
#include <cuda_runtime.h>
#include <math.h>
#include <stdint.h>

#define B_   2
#define S_   2048
#define D_   1024
#define H_   16
#define HD_  64
#define KJL  32
#define M_   (B_*S_)
#define NF   2048         // folded qkv width: 512 qjl | 512 kjl | 1024 v

// ---- scratch (device globals: allocation is forbidden) --------------------
__device__ float g_wf[NF*D_];     // folded weights, TRANSPOSED [n][k], tf32
__device__ float g_bf[NF];        // folded bias (fp32)
__device__ float g_x2[M_*NF];     // folded qkv output (tf32-rounded by epilogue)
__device__ float g_ao[M_*D_];     // attention output (tf32-rounded)
__device__ float g_xr[M_*D_];     // tf32-rounded input X
__device__ float g_wpt[D_*D_];    // W_proj TRANSPOSED [n][k], tf32

__device__ __forceinline__ float rtf32(float x) {
    asm("cvt.rna.tf32.f32 %0, %1;" : "=f"(x) : "f"(x));
    return x;
}
__device__ __forceinline__ void cpa16(uint32_t dst, const void* src) {
    asm volatile("cp.async.cg.shared.global [%0], [%1], 16;" :: "r"(dst), "l"(src));
}
__device__ __forceinline__ void cp_commit() {
    asm volatile("cp.async.commit_group;");
}
template<int N> __device__ __forceinline__ void cp_wait() {
    asm volatile("cp.async.wait_group %0;" :: "n"(N));
}
__device__ __forceinline__ void ldsm4(uint32_t& r0, uint32_t& r1,
                                      uint32_t& r2, uint32_t& r3, uint32_t addr) {
    asm volatile("ldmatrix.sync.aligned.m8n8.x4.shared.b16 {%0,%1,%2,%3}, [%4];"
                 : "=r"(r0), "=r"(r1), "=r"(r2), "=r"(r3) : "r"(addr));
}
__device__ __forceinline__ void mma8(float4& d, const uint32_t* a,
                                     uint32_t b0, uint32_t b1)
{
    asm volatile(
        "mma.sync.aligned.m16n8k8.row.col.f32.tf32.tf32.f32 "
        "{%0,%1,%2,%3},{%4,%5,%6,%7},{%8,%9},{%0,%1,%2,%3};"
        : "+f"(d.x), "+f"(d.y), "+f"(d.z), "+f"(d.w)
        : "r"(a[0]), "r"(a[1]), "r"(a[2]), "r"(a[3]), "r"(b0), "r"(b1));
}

// ===========================================================================
// Prep 1: tf32-round X
// ===========================================================================
__global__ void round_prep(const float* __restrict__ X, float* __restrict__ xr)
{
    int i = blockIdx.x * 256 + threadIdx.x;
    if (i < M_*D_) xr[i] = rtf32(X[i]);
}

// ===========================================================================
// Prep 2: tiled transpose + tf32 round.
// z=0: WpT[n][k] = rtf32(Wp[k][n])         (1024x1024, ld 1024, off 0)
// z=1: WfT[1024+n][k] = rtf32(Wat[k][2048+n]) (v-part, ld 3072, off 2048)
// grid (32, 32, 2), block (32, 8)
// ===========================================================================
__global__ void transpose_round(const float* __restrict__ Wp,
                                const float* __restrict__ Wat,
                                float* __restrict__ wpt, float* __restrict__ wfT)
{
    __shared__ float sm[32][33];
    const float* src; float* dst; int lds, off;
    if (blockIdx.z == 0) { src = Wp;  dst = wpt;              lds = 1024; off = 0;    }
    else                 { src = Wat; dst = wfT + 1024*D_;    lds = 3072; off = 2048; }
    const int bx = blockIdx.x * 32, by = blockIdx.y * 32;
    const int tx = threadIdx.x, ty = threadIdx.y;
    #pragma unroll
    for (int j = 0; j < 4; j++) {
        int r = ty*4 + j;
        sm[r][tx] = src[(long)(by + r)*lds + off + bx + tx];
    }
    __syncthreads();
    #pragma unroll
    for (int j = 0; j < 4; j++) {
        int r = ty*4 + j;
        dst[(long)(bx + r)*D_ + by + tx] = rtf32(sm[tx][r]);
    }
}

// ===========================================================================
// Prep 3: fold S_proj into q/k weights, output TRANSPOSED:
//   WfT[part*512 + h*32 + k][d] = rtf32(sum_e Wat[d][part*1024+h*64+e]*Sp[k][e])
// grid (8 d-chunks, 32 (part,h)), block 256
// ===========================================================================
__global__ __launch_bounds__(256)
void fold_qk(const float* __restrict__ Wat, const float* __restrict__ Sp,
             float* __restrict__ WfT)
{
    __shared__ float slab[128][65];
    __shared__ float sp[32][64];
    const int d0   = blockIdx.x * 128;
    const int ph   = blockIdx.y;
    const int part = ph >> 4, h = ph & 15;
    const int base = part*1024 + h*64;
    const int tid  = threadIdx.x;

    #pragma unroll
    for (int it = 0; it < 32; it++) {
        int i = tid + it*256;
        slab[i >> 6][i & 63] = Wat[(long)(d0 + (i >> 6))*(3*D_) + base + (i & 63)];
    }
    #pragma unroll
    for (int it = 0; it < 8; it++) {
        int i = tid + it*256;
        sp[i >> 6][i & 63] = Sp[i];
    }
    __syncthreads();

    const int dl = tid & 127;
    const int k0 = (tid >> 7) * 16;
    for (int k = k0; k < k0 + 16; k++) {
        float a = 0.f;
        #pragma unroll
        for (int e = 0; e < 64; e++) a += slab[dl][e] * sp[k][e];
        WfT[(long)(part*512 + h*32 + k)*D_ + d0 + dl] = rtf32(a);
    }
}

// ===========================================================================
// Prep 4: folded bias (fp32) — same math/order as before
// ===========================================================================
__global__ void fold_bias(const float* __restrict__ bat,
                          const float* __restrict__ Sp, float* __restrict__ bf)
{
    const int i = blockIdx.x * 256 + threadIdx.x;
    if (i >= NF) return;
    if (i < 1024) {
        const int part = i >> 9, hk = i & 511, h = hk >> 5, k = hk & 31;
        float a = 0.f;
        #pragma unroll
        for (int e = 0; e < HD_; e++) a += bat[part*1024 + h*HD_ + e] * Sp[k*HD_ + e];
        bf[i] = a;
    } else {
        bf[i] = bat[2048 + (i - 1024)];
    }
}

// ===========================================================================
// TF32 GEMM (TN): C[M,N] = A[M,K] @ BT[N,K]^T + bias.
// Raw mma.m16n8k8 + ldmatrix for BOTH operands (both K-major in smem).
// 128x128x16 block tile, 128 thr = 4 warps (2m x 2n), warp tile 64x64.
// Per chunk/warp: 16 LDSM.x4 + 64 HMMA. 3-stage cp.async, 2 blocks/SM.
// Bias folded into accumulator init. Optional tf32 rounding of C.
// ===========================================================================
#define GBM 128
#define GBN 128
#define GBK 16
#define LDT 20
#define STG 3
#define TSTAGE (128*LDT*4)

__global__ __launch_bounds__(128, 2)
void tf32_gemm_tn(const float* __restrict__ A, const float* __restrict__ BT,
                  const float* __restrict__ bias, float* __restrict__ C,
                  int M, int N, int K, int roundC)
{
    extern __shared__ float dyn[];
    float* As = dyn;                       // [STG][128][LDT]
    float* Bs = dyn + STG*128*LDT;         // [STG][128][LDT]

    const int tid  = threadIdx.x;
    const int wid  = tid >> 5;
    const int lane = tid & 31;
    const int g    = lane >> 2;
    const int t    = lane & 3;
    const int brow = blockIdx.y * GBM;
    const int bcol = blockIdx.x * GBN;
    const int wm   = (wid & 1) * 64;
    const int wn   = (wid >> 1) * 64;

    // ---- accumulators initialized with bias (same order as before) --------
    float4 acc[4][8];
    #pragma unroll
    for (int nt = 0; nt < 8; nt++) {
        float2 bb = *(const float2*)&bias[bcol + wn + nt*8 + 2*t];
        #pragma unroll
        for (int i = 0; i < 4; i++)
            acc[i][nt] = make_float4(bb.x, bb.y, bb.x, bb.y);
    }

    // ---- cp.async indexing (identical pattern for A and B tiles) ----------
    const int lr = tid >> 2;            // row 0..31 (+32 per pass)
    const int lc = (tid & 3) << 2;      // float col 0,4,8,12
    const float* Ag = A  + (long)(brow + lr)*K + lc;
    const float* Bg = BT + (long)(bcol + lr)*K + lc;
    const uint32_t sA = (uint32_t)__cvta_generic_to_shared(As);
    const uint32_t sB = (uint32_t)__cvta_generic_to_shared(Bs);
    const uint32_t ldoff = (lr*LDT + lc) * 4;

    // ---- ldmatrix per-thread offsets (within a stage) ----------------------
    // A frag: row = wm + i*16 + (lane&15), col = kk2*8 + ((lane>>4)<<2)
    // B frag: row = wn + nt*8 + (lane&7),  col = ((lane>>3)<<2)   (covers k 0..15)
    const uint32_t a_off = (((wm + (lane & 15))*LDT) + ((lane >> 4) << 2)) * 4;
    const uint32_t b_off = (((wn + (lane & 7 ))*LDT) + ((lane >> 3) << 2)) * 4;

    const int KC = K / GBK;
    int fetch = 0;

    #pragma unroll
    for (int p = 0; p < STG - 1; p++) {
        #pragma unroll
        for (int i = 0; i < 4; i++) {
            cpa16(sA + p*TSTAGE + ldoff + i*(32*LDT*4), Ag + (long)i*32*K + fetch*GBK);
            cpa16(sB + p*TSTAGE + ldoff + i*(32*LDT*4), Bg + (long)i*32*K + fetch*GBK);
        }
        cp_commit();
        fetch++;
    }

    int s = 0;
    for (int c = 0; c < KC; c++) {
        cp_wait<STG - 2>();
        __syncthreads();

        const uint32_t aS = sA + s*TSTAGE;
        const uint32_t bS = sB + s*TSTAGE;

        uint32_t bfr[8][4];
        #pragma unroll
        for (int nt = 0; nt < 8; nt++)
            ldsm4(bfr[nt][0], bfr[nt][1], bfr[nt][2], bfr[nt][3],
                  bS + b_off + nt*(8*LDT*4));

        #pragma unroll
        for (int kk2 = 0; kk2 < 2; kk2++) {
            uint32_t af[4][4];
            #pragma unroll
            for (int i = 0; i < 4; i++)
                ldsm4(af[i][0], af[i][1], af[i][2], af[i][3],
                      aS + a_off + (i*16*LDT + kk2*8)*4);
            #pragma unroll
            for (int i = 0; i < 4; i++)
                #pragma unroll
                for (int nt = 0; nt < 8; nt++)
                    mma8(acc[i][nt], af[i], bfr[nt][kk2*2], bfr[nt][kk2*2 + 1]);
        }

        if (fetch < KC) {
            const int p = (s + STG - 1) >= STG ? s - 1 : s + STG - 1;
            #pragma unroll
            for (int i = 0; i < 4; i++) {
                cpa16(sA + p*TSTAGE + ldoff + i*(32*LDT*4), Ag + (long)i*32*K + fetch*GBK);
                cpa16(sB + p*TSTAGE + ldoff + i*(32*LDT*4), Bg + (long)i*32*K + fetch*GBK);
            }
            fetch++;
        }
        cp_commit();
        s = (s + 1 == STG) ? 0 : s + 1;
    }

    // ---- epilogue ----------------------------------------------------------
    #pragma unroll
    for (int i = 0; i < 4; i++) {
        const long r0 = brow + wm + i*16 + g;
        #pragma unroll
        for (int nt = 0; nt < 8; nt++) {
            const int c0 = bcol + wn + nt*8 + 2*t;
            float4 v = acc[i][nt];
            if (roundC) {
                v.x = rtf32(v.x); v.y = rtf32(v.y);
                v.z = rtf32(v.z); v.w = rtf32(v.w);
            }
            *(float2*)&C[r0*N + c0]       = make_float2(v.x, v.y);
            *(float2*)&C[(r0 + 8)*N + c0] = make_float2(v.z, v.w);
        }
    }
}

// ===========================================================================
// Tensor-core causal flash attention (m16n8k8 tf32) — unchanged from best.
// x2 is pre-rounded tf32; double-buffered cp.async K/V tiles.
// 128 thr = 4 warps, 64 queries/block. grid = (S/64, H, B), heavy tiles first.
// ===========================================================================
#define LDK 36
#define LDV 68
#define KBYTES (64*LDK*4)
#define VBYTES (64*LDV*4)

__global__ __launch_bounds__(128, 4)
void attn_mma(const float* __restrict__ x2, float* __restrict__ ao)
{
    extern __shared__ float smem[];
    float* Ks = smem;                 // [2][64*LDK]
    float* Vs = smem + 2*64*LDK;      // [2][64*LDV]

    const int tid  = threadIdx.x;
    const int w    = tid >> 5;
    const int lane = tid & 31;
    const int g    = lane >> 2;
    const int t    = lane & 3;
    const int h    = blockIdx.y;
    const int b    = blockIdx.z;
    const int qt   = gridDim.x - 1 - blockIdx.x;
    const int q0   = qt * 64;

    const uint32_t sK = (uint32_t)__cvta_generic_to_shared(Ks);
    const uint32_t sV = (uint32_t)__cvta_generic_to_shared(Vs);

    const int kr = tid >> 3, kc = (tid & 7) << 2;
    const int vr = tid >> 4, vc = (tid & 15) << 2;
    const float* kbase = x2 + (long)(b*S_) * NF + 512  + h*KJL;
    const float* vbase = x2 + (long)(b*S_) * NF + 1024 + h*HD_;

    #define LOAD_TILE(kt_, bb_)                                                 \
    {                                                                           \
        const float* kb = kbase + (long)((kt_)*64 + kr) * NF + kc;              \
        const float* vb = vbase + (long)((kt_)*64 + vr) * NF + vc;              \
        uint32_t dk = sK + (bb_)*KBYTES + (kr*LDK + kc)*4;                      \
        uint32_t dv = sV + (bb_)*VBYTES + (vr*LDV + vc)*4;                      \
        _Pragma("unroll")                                                       \
        for (int i_ = 0; i_ < 4; i_++)                                          \
            cpa16(dk + i_*(16*LDK*4), kb + (long)i_*16*NF);                     \
        _Pragma("unroll")                                                       \
        for (int i_ = 0; i_ < 8; i_++)                                          \
            cpa16(dv + i_*(8*LDV*4),  vb + (long)i_*8*NF);                      \
    }

    uint32_t qf[4][4];
    {
        const float* qb = x2 + (long)(b*S_ + q0) * NF + h*KJL;
        #pragma unroll
        for (int ks = 0; ks < 4; ks++) {
            qf[ks][0] = __float_as_uint(qb[(long)(w*16 + g    )*NF + ks*8 + t    ]);
            qf[ks][1] = __float_as_uint(qb[(long)(w*16 + g + 8)*NF + ks*8 + t    ]);
            qf[ks][2] = __float_as_uint(qb[(long)(w*16 + g    )*NF + ks*8 + t + 4]);
            qf[ks][3] = __float_as_uint(qb[(long)(w*16 + g + 8)*NF + ks*8 + t + 4]);
        }
    }

    float4 oacc[8];
    #pragma unroll
    for (int nt = 0; nt < 8; nt++) oacc[nt] = make_float4(0.f, 0.f, 0.f, 0.f);
    float m0 = -1e30f, m1 = -1e30f, l0 = 0.f, l1 = 0.f;

    const int R0 = q0 + w*16 + g;
    const int R1 = R0 + 8;
    const int nkt = qt + 1;
    const int lq0 = (lane & ~3) | (t >> 1);
    const int lq1 = lq0 + 2;

    LOAD_TILE(0, 0);
    cp_commit();

    int buf = 0;
    for (int kt = 0; kt < nkt; kt++) {
        if (kt + 1 < nkt) {
            LOAD_TILE(kt + 1, buf ^ 1);
            cp_commit();
            cp_wait<1>();
        } else {
            cp_wait<0>();
        }
        __syncthreads();

        const float* Kb = Ks + buf * (64*LDK);
        const float* Vb = Vs + buf * (64*LDV);

        float4 sa[8];
        #pragma unroll
        for (int nt = 0; nt < 8; nt++) {
            sa[nt] = make_float4(0.f, 0.f, 0.f, 0.f);
            #pragma unroll
            for (int ks = 0; ks < 4; ks++) {
                uint32_t b0 = __float_as_uint(Kb[(nt*8 + g)*LDK + ks*8 + t    ]);
                uint32_t b1 = __float_as_uint(Kb[(nt*8 + g)*LDK + ks*8 + t + 4]);
                mma8(sa[nt], qf[ks], b0, b1);
            }
        }

        float mx0 = -1e30f, mx1 = -1e30f;
        #pragma unroll
        for (int nt = 0; nt < 8; nt++) {
            const int c0 = kt*64 + nt*8 + 2*t;
            const int c1 = c0 + 1;
            sa[nt].x = (c0 <= R0) ? sa[nt].x * 0.125f : -1e30f;
            sa[nt].y = (c1 <= R0) ? sa[nt].y * 0.125f : -1e30f;
            sa[nt].z = (c0 <= R1) ? sa[nt].z * 0.125f : -1e30f;
            sa[nt].w = (c1 <= R1) ? sa[nt].w * 0.125f : -1e30f;
            mx0 = fmaxf(mx0, fmaxf(sa[nt].x, sa[nt].y));
            mx1 = fmaxf(mx1, fmaxf(sa[nt].z, sa[nt].w));
        }
        mx0 = fmaxf(mx0, __shfl_xor_sync(0xffffffff, mx0, 1));
        mx0 = fmaxf(mx0, __shfl_xor_sync(0xffffffff, mx0, 2));
        mx1 = fmaxf(mx1, __shfl_xor_sync(0xffffffff, mx1, 1));
        mx1 = fmaxf(mx1, __shfl_xor_sync(0xffffffff, mx1, 2));

        const float nm0 = fmaxf(m0, mx0);
        const float nm1 = fmaxf(m1, mx1);
        const float sc0 = __expf(m0 - nm0);
        const float sc1 = __expf(m1 - nm1);

        float ps0 = 0.f, ps1 = 0.f;
        #pragma unroll
        for (int nt = 0; nt < 8; nt++) {
            sa[nt].x = __expf(sa[nt].x - nm0);
            sa[nt].y = __expf(sa[nt].y - nm0);
            sa[nt].z = __expf(sa[nt].z - nm1);
            sa[nt].w = __expf(sa[nt].w - nm1);
            ps0 += sa[nt].x + sa[nt].y;
            ps1 += sa[nt].z + sa[nt].w;
        }
        ps0 += __shfl_xor_sync(0xffffffff, ps0, 1);
        ps0 += __shfl_xor_sync(0xffffffff, ps0, 2);
        ps1 += __shfl_xor_sync(0xffffffff, ps1, 1);
        ps1 += __shfl_xor_sync(0xffffffff, ps1, 2);

        l0 = l0 * sc0 + ps0;  m0 = nm0;
        l1 = l1 * sc1 + ps1;  m1 = nm1;

        #pragma unroll
        for (int nt = 0; nt < 8; nt++) {
            oacc[nt].x *= sc0;  oacc[nt].y *= sc0;
            oacc[nt].z *= sc1;  oacc[nt].w *= sc1;
        }

        #pragma unroll
        for (int ks = 0; ks < 8; ks++) {
            float x0 = __shfl_sync(0xffffffff, sa[ks].x, lq0);
            float y0 = __shfl_sync(0xffffffff, sa[ks].y, lq0);
            float z0 = __shfl_sync(0xffffffff, sa[ks].z, lq0);
            float w0 = __shfl_sync(0xffffffff, sa[ks].w, lq0);
            float x1 = __shfl_sync(0xffffffff, sa[ks].x, lq1);
            float y1 = __shfl_sync(0xffffffff, sa[ks].y, lq1);
            float z1 = __shfl_sync(0xffffffff, sa[ks].z, lq1);
            float w1 = __shfl_sync(0xffffffff, sa[ks].w, lq1);
            uint32_t pa[4];
            pa[0] = __float_as_uint(rtf32((t & 1) ? y0 : x0));
            pa[1] = __float_as_uint(rtf32((t & 1) ? w0 : z0));
            pa[2] = __float_as_uint(rtf32((t & 1) ? y1 : x1));
            pa[3] = __float_as_uint(rtf32((t & 1) ? w1 : z1));

            const int kr0 = (ks*8 + t    ) * LDV + g;
            const int kr1 = (ks*8 + t + 4) * LDV + g;
            #pragma unroll
            for (int nt = 0; nt < 8; nt++) {
                uint32_t b0 = __float_as_uint(Vb[kr0 + nt*8]);
                uint32_t b1 = __float_as_uint(Vb[kr1 + nt*8]);
                mma8(oacc[nt], pa, b0, b1);
            }
        }
        __syncthreads();
        buf ^= 1;
    }

    const float inv0 = 1.f / l0;
    const float inv1 = 1.f / l1;
    float* o0 = ao + (long)(b*S_ + R0) * D_ + h*HD_;
    float* o1 = ao + (long)(b*S_ + R1) * D_ + h*HD_;
    #pragma unroll
    for (int nt = 0; nt < 8; nt++) {
        *(float2*)(o0 + nt*8 + 2*t) =
            make_float2(rtf32(oacc[nt].x * inv0), rtf32(oacc[nt].y * inv0));
        *(float2*)(o1 + nt*8 + 2*t) =
            make_float2(rtf32(oacc[nt].z * inv1), rtf32(oacc[nt].w * inv1));
    }
}

// ===========================================================================
extern "C" void kernel_launch(void* const* d_in, const int* in_sizes, int n_in,
                              void* d_out, int out_size)
{
    const float* X    = (const float*)d_in[0];
    const float* Wat  = (const float*)d_in[1];
    const float* bat  = (const float*)d_in[2];
    const float* Sp   = (const float*)d_in[3];
    const float* Wp   = (const float*)d_in[4];
    const float* bp   = (const float*)d_in[5];
    float* out = (float*)d_out;

    float *wf, *bf, *x2, *ao, *xr, *wpt;
    cudaGetSymbolAddress((void**)&wf,  g_wf);
    cudaGetSymbolAddress((void**)&bf,  g_bf);
    cudaGetSymbolAddress((void**)&x2,  g_x2);
    cudaGetSymbolAddress((void**)&ao,  g_ao);
    cudaGetSymbolAddress((void**)&xr,  g_xr);
    cudaGetSymbolAddress((void**)&wpt, g_wpt);

    const int gemmSmem = 2 * STG * 128 * LDT * 4;             // 61440 B
    const int attnSmem = 2 * (64*LDK + 64*LDV) * 4;           // 53248 B
    cudaFuncSetAttribute(tf32_gemm_tn,
                         cudaFuncAttributeMaxDynamicSharedMemorySize, gemmSmem);
    cudaFuncSetAttribute(attn_mma,
                         cudaFuncAttributeMaxDynamicSharedMemorySize, attnSmem);

    // 0. prep: round X; transpose+round Wp and v-part of Wat; fold q/k; bias
    round_prep<<<(M_*D_ + 255)/256, 256>>>(X, xr);
    dim3 gt(32, 32, 2);
    transpose_round<<<gt, dim3(32, 8)>>>(Wp, Wat, wpt, wf);
    fold_qk<<<dim3(8, 32), 256>>>(Wat, Sp, wf);
    fold_bias<<<NF/256, 256>>>(bat, Sp, bf);

    // 1. folded QKV GEMM (epilogue rounds x2 to tf32)
    dim3 g1(NF/GBN, M_/GBM);
    tf32_gemm_tn<<<g1, 128, gemmSmem>>>(xr, wf, bf, x2, M_, NF, D_, 1);

    // 2. causal flash attention
    dim3 g3(S_/64, H_, B_);
    attn_mma<<<g3, 128, attnSmem>>>(x2, ao);

    // 3. output projection GEMM (raw fp32 output)
    dim3 g4(D_/GBN, M_/GBM);
    tf32_gemm_tn<<<g4, 128, gemmSmem>>>(ao, wpt, bp, out, M_, D_, D_, 0);
}

// round 14
// speedup vs baseline: 2.7499x; 1.4850x over previous
#include <cuda_runtime.h>
#include <math.h>
#include <stdint.h>

#define B_   2
#define S_   2048
#define D_   1024
#define H_   16
#define HD_  64
#define KJL  32
#define M_   (B_*S_)
#define NF   2048         // folded qkv width: 512 qjl | 512 kjl | 1024 v

// ---- scratch (device globals: allocation is forbidden) --------------------
__device__ float g_wf[NF*D_];     // folded weights, TRANSPOSED [n][k], tf32
__device__ float g_bf[NF];        // folded bias (fp32)
__device__ float g_x2[M_*NF];     // folded qkv output (tf32-rounded by epilogue)
__device__ float g_ao[M_*D_];     // attention output (tf32-rounded)
__device__ float g_xr[M_*D_];     // tf32-rounded input X
__device__ float g_wpt[D_*D_];    // W_proj TRANSPOSED [n][k], tf32

__device__ __forceinline__ float rtf32(float x) {
    asm("cvt.rna.tf32.f32 %0, %1;" : "=f"(x) : "f"(x));
    return x;
}
__device__ __forceinline__ void cpa16(uint32_t dst, const void* src) {
    asm volatile("cp.async.cg.shared.global [%0], [%1], 16;" :: "r"(dst), "l"(src));
}
__device__ __forceinline__ void cp_commit() {
    asm volatile("cp.async.commit_group;");
}
template<int N> __device__ __forceinline__ void cp_wait() {
    asm volatile("cp.async.wait_group %0;" :: "n"(N));
}
__device__ __forceinline__ void ldsm4(uint32_t& r0, uint32_t& r1,
                                      uint32_t& r2, uint32_t& r3, uint32_t addr) {
    asm volatile("ldmatrix.sync.aligned.m8n8.x4.shared.b16 {%0,%1,%2,%3}, [%4];"
                 : "=r"(r0), "=r"(r1), "=r"(r2), "=r"(r3) : "r"(addr));
}
__device__ __forceinline__ void mma8(float4& d, const uint32_t* a,
                                     uint32_t b0, uint32_t b1)
{
    asm volatile(
        "mma.sync.aligned.m16n8k8.row.col.f32.tf32.tf32.f32 "
        "{%0,%1,%2,%3},{%4,%5,%6,%7},{%8,%9},{%0,%1,%2,%3};"
        : "+f"(d.x), "+f"(d.y), "+f"(d.z), "+f"(d.w)
        : "r"(a[0]), "r"(a[1]), "r"(a[2]), "r"(a[3]), "r"(b0), "r"(b1));
}

// ===========================================================================
// Merged prep: ONE launch does all preprocessing (prev: 4 serialized launches
// costing ~15-18us each in latency).
//   blocks [0, 16384)          : xr = rtf32(X)                (256 elems/blk)
//   blocks [16384, 18432)      : transpose+round Wp -> wpt, v(Wat) -> wf
//   blocks [18432, 18688)      : fold q/k weights (transposed) -> wf
//   blocks [18688, 18696)      : folded bias -> bf
// Per-output arithmetic identical to the previous separate kernels.
// ===========================================================================
#define NB_SPLIT 16384
#define NB_TR    2048
#define NB_FOLD  256
#define NB_BIAS  8
#define NB_ALL   (NB_SPLIT + NB_TR + NB_FOLD + NB_BIAS)

__global__ __launch_bounds__(256)
void prep_all(const float* __restrict__ X,   const float* __restrict__ Wat,
              const float* __restrict__ bat, const float* __restrict__ Sp,
              const float* __restrict__ Wp,
              float* __restrict__ xr,  float* __restrict__ wpt,
              float* __restrict__ wf,  float* __restrict__ bf)
{
    __shared__ float sbuf[128*65 + 32*64];     // max of all users (41.5 KB)
    const int bid = blockIdx.x;
    const int tid = threadIdx.x;

    if (bid < NB_SPLIT) {
        // ---- tf32-round X ------------------------------------------------
        int i = bid * 256 + tid;
        xr[i] = rtf32(X[i]);

    } else if (bid < NB_SPLIT + NB_TR) {
        // ---- tiled transpose + round ------------------------------------
        float (*sm)[33] = (float(*)[33])sbuf;
        const int rem = bid - NB_SPLIT;
        const int z  = rem >> 10;               // 0..1
        const int bx = (rem & 31) * 32;
        const int by = ((rem >> 5) & 31) * 32;
        const float* src; float* dst; int lds, off;
        if (z == 0) { src = Wp;  dst = wpt;           lds = 1024; off = 0;    }
        else        { src = Wat; dst = wf + 1024*D_;  lds = 3072; off = 2048; }
        const int tx = tid & 31, ty = tid >> 5;
        #pragma unroll
        for (int j = 0; j < 4; j++) {
            int r = ty*4 + j;
            sm[r][tx] = src[(long)(by + r)*lds + off + bx + tx];
        }
        __syncthreads();
        #pragma unroll
        for (int j = 0; j < 4; j++) {
            int r = ty*4 + j;
            dst[(long)(bx + r)*D_ + by + tx] = rtf32(sm[tx][r]);
        }

    } else if (bid < NB_SPLIT + NB_TR + NB_FOLD) {
        // ---- fold S_proj into q/k weights (transposed output) -----------
        float (*slab)[65] = (float(*)[65])sbuf;
        float (*sp)[64]   = (float(*)[64])(sbuf + 128*65);
        const int rem  = bid - NB_SPLIT - NB_TR;
        const int d0   = (rem & 7) * 128;
        const int ph   = rem >> 3;               // 0..31
        const int part = ph >> 4, h = ph & 15;
        const int base = part*1024 + h*64;

        #pragma unroll
        for (int it = 0; it < 32; it++) {
            int i = tid + it*256;
            slab[i >> 6][i & 63] = Wat[(long)(d0 + (i >> 6))*(3*D_) + base + (i & 63)];
        }
        #pragma unroll
        for (int it = 0; it < 8; it++) {
            int i = tid + it*256;
            sp[i >> 6][i & 63] = Sp[i];
        }
        __syncthreads();

        const int dl = tid & 127;
        const int k0 = (tid >> 7) * 16;
        for (int k = k0; k < k0 + 16; k++) {
            float a = 0.f;
            #pragma unroll
            for (int e = 0; e < 64; e++) a += slab[dl][e] * sp[k][e];
            wf[(long)(part*512 + h*32 + k)*D_ + d0 + dl] = rtf32(a);
        }

    } else {
        // ---- folded bias -------------------------------------------------
        const int i = (bid - NB_SPLIT - NB_TR - NB_FOLD) * 256 + tid;
        if (i < NF) {
            if (i < 1024) {
                const int part = i >> 9, hk = i & 511, h = hk >> 5, k = hk & 31;
                float a = 0.f;
                #pragma unroll
                for (int e = 0; e < HD_; e++)
                    a += bat[part*1024 + h*HD_ + e] * Sp[k*HD_ + e];
                bf[i] = a;
            } else {
                bf[i] = bat[2048 + (i - 1024)];
            }
        }
    }
}

// ===========================================================================
// TF32 GEMM (TN): C[M,N] = A[M,K] @ BT[N,K]^T + bias.
// Raw mma.m16n8k8 + ldmatrix for BOTH operands (both K-major in smem).
// 128x128x16 block tile, 128 thr = 4 warps (2m x 2n), warp tile 64x64.
// Per chunk/warp: 16 LDSM.x4 + 64 HMMA. 3-stage cp.async, 2 blocks/SM.
// Bias folded into accumulator init. Optional tf32 rounding of C.
// ===========================================================================
#define GBM 128
#define GBN 128
#define GBK 16
#define LDT 20
#define STG 3
#define TSTAGE (128*LDT*4)

__global__ __launch_bounds__(128, 2)
void tf32_gemm_tn(const float* __restrict__ A, const float* __restrict__ BT,
                  const float* __restrict__ bias, float* __restrict__ C,
                  int M, int N, int K, int roundC)
{
    extern __shared__ float dyn[];
    float* As = dyn;                       // [STG][128][LDT]
    float* Bs = dyn + STG*128*LDT;         // [STG][128][LDT]

    const int tid  = threadIdx.x;
    const int wid  = tid >> 5;
    const int lane = tid & 31;
    const int g    = lane >> 2;
    const int t    = lane & 3;
    const int brow = blockIdx.y * GBM;
    const int bcol = blockIdx.x * GBN;
    const int wm   = (wid & 1) * 64;
    const int wn   = (wid >> 1) * 64;

    // ---- accumulators initialized with bias --------------------------------
    float4 acc[4][8];
    #pragma unroll
    for (int nt = 0; nt < 8; nt++) {
        float2 bb = *(const float2*)&bias[bcol + wn + nt*8 + 2*t];
        #pragma unroll
        for (int i = 0; i < 4; i++)
            acc[i][nt] = make_float4(bb.x, bb.y, bb.x, bb.y);
    }

    // ---- cp.async indexing --------------------------------------------------
    const int lr = tid >> 2;            // row 0..31 (+32 per pass)
    const int lc = (tid & 3) << 2;      // float col 0,4,8,12
    const float* Ag = A  + (long)(brow + lr)*K + lc;
    const float* Bg = BT + (long)(bcol + lr)*K + lc;
    const uint32_t sA = (uint32_t)__cvta_generic_to_shared(As);
    const uint32_t sB = (uint32_t)__cvta_generic_to_shared(Bs);
    const uint32_t ldoff = (lr*LDT + lc) * 4;

    // ---- ldmatrix per-thread offsets ----------------------------------------
    const uint32_t a_off = (((wm + (lane & 15))*LDT) + ((lane >> 4) << 2)) * 4;
    const uint32_t b_off = (((wn + (lane & 7 ))*LDT) + ((lane >> 3) << 2)) * 4;

    const int KC = K / GBK;
    int fetch = 0;

    #pragma unroll
    for (int p = 0; p < STG - 1; p++) {
        #pragma unroll
        for (int i = 0; i < 4; i++) {
            cpa16(sA + p*TSTAGE + ldoff + i*(32*LDT*4), Ag + (long)i*32*K + fetch*GBK);
            cpa16(sB + p*TSTAGE + ldoff + i*(32*LDT*4), Bg + (long)i*32*K + fetch*GBK);
        }
        cp_commit();
        fetch++;
    }

    int s = 0;
    for (int c = 0; c < KC; c++) {
        cp_wait<STG - 2>();
        __syncthreads();

        const uint32_t aS = sA + s*TSTAGE;
        const uint32_t bS = sB + s*TSTAGE;

        uint32_t bfr[8][4];
        #pragma unroll
        for (int nt = 0; nt < 8; nt++)
            ldsm4(bfr[nt][0], bfr[nt][1], bfr[nt][2], bfr[nt][3],
                  bS + b_off + nt*(8*LDT*4));

        #pragma unroll
        for (int kk2 = 0; kk2 < 2; kk2++) {
            uint32_t af[4][4];
            #pragma unroll
            for (int i = 0; i < 4; i++)
                ldsm4(af[i][0], af[i][1], af[i][2], af[i][3],
                      aS + a_off + (i*16*LDT + kk2*8)*4);
            #pragma unroll
            for (int i = 0; i < 4; i++)
                #pragma unroll
                for (int nt = 0; nt < 8; nt++)
                    mma8(acc[i][nt], af[i], bfr[nt][kk2*2], bfr[nt][kk2*2 + 1]);
        }

        if (fetch < KC) {
            const int p = (s + STG - 1) >= STG ? s - 1 : s + STG - 1;
            #pragma unroll
            for (int i = 0; i < 4; i++) {
                cpa16(sA + p*TSTAGE + ldoff + i*(32*LDT*4), Ag + (long)i*32*K + fetch*GBK);
                cpa16(sB + p*TSTAGE + ldoff + i*(32*LDT*4), Bg + (long)i*32*K + fetch*GBK);
            }
            fetch++;
        }
        cp_commit();
        s = (s + 1 == STG) ? 0 : s + 1;
    }

    // ---- epilogue ----------------------------------------------------------
    #pragma unroll
    for (int i = 0; i < 4; i++) {
        const long r0 = brow + wm + i*16 + g;
        #pragma unroll
        for (int nt = 0; nt < 8; nt++) {
            const int c0 = bcol + wn + nt*8 + 2*t;
            float4 v = acc[i][nt];
            if (roundC) {
                v.x = rtf32(v.x); v.y = rtf32(v.y);
                v.z = rtf32(v.z); v.w = rtf32(v.w);
            }
            *(float2*)&C[r0*N + c0]       = make_float2(v.x, v.y);
            *(float2*)&C[(r0 + 8)*N + c0] = make_float2(v.z, v.w);
        }
    }
}

// ===========================================================================
// Tensor-core causal flash attention (m16n8k8 tf32) — unchanged (proven).
// x2 is pre-rounded tf32; double-buffered cp.async K/V tiles.
// 128 thr = 4 warps, 64 queries/block. grid = (S/64, H, B), heavy tiles first.
// ===========================================================================
#define LDK 36
#define LDV 68
#define KBYTES (64*LDK*4)
#define VBYTES (64*LDV*4)

__global__ __launch_bounds__(128, 4)
void attn_mma(const float* __restrict__ x2, float* __restrict__ ao)
{
    extern __shared__ float smem[];
    float* Ks = smem;                 // [2][64*LDK]
    float* Vs = smem + 2*64*LDK;      // [2][64*LDV]

    const int tid  = threadIdx.x;
    const int w    = tid >> 5;
    const int lane = tid & 31;
    const int g    = lane >> 2;
    const int t    = lane & 3;
    const int h    = blockIdx.y;
    const int b    = blockIdx.z;
    const int qt   = gridDim.x - 1 - blockIdx.x;
    const int q0   = qt * 64;

    const uint32_t sK = (uint32_t)__cvta_generic_to_shared(Ks);
    const uint32_t sV = (uint32_t)__cvta_generic_to_shared(Vs);

    const int kr = tid >> 3, kc = (tid & 7) << 2;
    const int vr = tid >> 4, vc = (tid & 15) << 2;
    const float* kbase = x2 + (long)(b*S_) * NF + 512  + h*KJL;
    const float* vbase = x2 + (long)(b*S_) * NF + 1024 + h*HD_;

    #define LOAD_TILE(kt_, bb_)                                                 \
    {                                                                           \
        const float* kb = kbase + (long)((kt_)*64 + kr) * NF + kc;              \
        const float* vb = vbase + (long)((kt_)*64 + vr) * NF + vc;              \
        uint32_t dk = sK + (bb_)*KBYTES + (kr*LDK + kc)*4;                      \
        uint32_t dv = sV + (bb_)*VBYTES + (vr*LDV + vc)*4;                      \
        _Pragma("unroll")                                                       \
        for (int i_ = 0; i_ < 4; i_++)                                          \
            cpa16(dk + i_*(16*LDK*4), kb + (long)i_*16*NF);                     \
        _Pragma("unroll")                                                       \
        for (int i_ = 0; i_ < 8; i_++)                                          \
            cpa16(dv + i_*(8*LDV*4),  vb + (long)i_*8*NF);                      \
    }

    uint32_t qf[4][4];
    {
        const float* qb = x2 + (long)(b*S_ + q0) * NF + h*KJL;
        #pragma unroll
        for (int ks = 0; ks < 4; ks++) {
            qf[ks][0] = __float_as_uint(qb[(long)(w*16 + g    )*NF + ks*8 + t    ]);
            qf[ks][1] = __float_as_uint(qb[(long)(w*16 + g + 8)*NF + ks*8 + t    ]);
            qf[ks][2] = __float_as_uint(qb[(long)(w*16 + g    )*NF + ks*8 + t + 4]);
            qf[ks][3] = __float_as_uint(qb[(long)(w*16 + g + 8)*NF + ks*8 + t + 4]);
        }
    }

    float4 oacc[8];
    #pragma unroll
    for (int nt = 0; nt < 8; nt++) oacc[nt] = make_float4(0.f, 0.f, 0.f, 0.f);
    float m0 = -1e30f, m1 = -1e30f, l0 = 0.f, l1 = 0.f;

    const int R0 = q0 + w*16 + g;
    const int R1 = R0 + 8;
    const int nkt = qt + 1;
    const int lq0 = (lane & ~3) | (t >> 1);
    const int lq1 = lq0 + 2;

    LOAD_TILE(0, 0);
    cp_commit();

    int buf = 0;
    for (int kt = 0; kt < nkt; kt++) {
        if (kt + 1 < nkt) {
            LOAD_TILE(kt + 1, buf ^ 1);
            cp_commit();
            cp_wait<1>();
        } else {
            cp_wait<0>();
        }
        __syncthreads();

        const float* Kb = Ks + buf * (64*LDK);
        const float* Vb = Vs + buf * (64*LDV);

        float4 sa[8];
        #pragma unroll
        for (int nt = 0; nt < 8; nt++) {
            sa[nt] = make_float4(0.f, 0.f, 0.f, 0.f);
            #pragma unroll
            for (int ks = 0; ks < 4; ks++) {
                uint32_t b0 = __float_as_uint(Kb[(nt*8 + g)*LDK + ks*8 + t    ]);
                uint32_t b1 = __float_as_uint(Kb[(nt*8 + g)*LDK + ks*8 + t + 4]);
                mma8(sa[nt], qf[ks], b0, b1);
            }
        }

        float mx0 = -1e30f, mx1 = -1e30f;
        #pragma unroll
        for (int nt = 0; nt < 8; nt++) {
            const int c0 = kt*64 + nt*8 + 2*t;
            const int c1 = c0 + 1;
            sa[nt].x = (c0 <= R0) ? sa[nt].x * 0.125f : -1e30f;
            sa[nt].y = (c1 <= R0) ? sa[nt].y * 0.125f : -1e30f;
            sa[nt].z = (c0 <= R1) ? sa[nt].z * 0.125f : -1e30f;
            sa[nt].w = (c1 <= R1) ? sa[nt].w * 0.125f : -1e30f;
            mx0 = fmaxf(mx0, fmaxf(sa[nt].x, sa[nt].y));
            mx1 = fmaxf(mx1, fmaxf(sa[nt].z, sa[nt].w));
        }
        mx0 = fmaxf(mx0, __shfl_xor_sync(0xffffffff, mx0, 1));
        mx0 = fmaxf(mx0, __shfl_xor_sync(0xffffffff, mx0, 2));
        mx1 = fmaxf(mx1, __shfl_xor_sync(0xffffffff, mx1, 1));
        mx1 = fmaxf(mx1, __shfl_xor_sync(0xffffffff, mx1, 2));

        const float nm0 = fmaxf(m0, mx0);
        const float nm1 = fmaxf(m1, mx1);
        const float sc0 = __expf(m0 - nm0);
        const float sc1 = __expf(m1 - nm1);

        float ps0 = 0.f, ps1 = 0.f;
        #pragma unroll
        for (int nt = 0; nt < 8; nt++) {
            sa[nt].x = __expf(sa[nt].x - nm0);
            sa[nt].y = __expf(sa[nt].y - nm0);
            sa[nt].z = __expf(sa[nt].z - nm1);
            sa[nt].w = __expf(sa[nt].w - nm1);
            ps0 += sa[nt].x + sa[nt].y;
            ps1 += sa[nt].z + sa[nt].w;
        }
        ps0 += __shfl_xor_sync(0xffffffff, ps0, 1);
        ps0 += __shfl_xor_sync(0xffffffff, ps0, 2);
        ps1 += __shfl_xor_sync(0xffffffff, ps1, 1);
        ps1 += __shfl_xor_sync(0xffffffff, ps1, 2);

        l0 = l0 * sc0 + ps0;  m0 = nm0;
        l1 = l1 * sc1 + ps1;  m1 = nm1;

        #pragma unroll
        for (int nt = 0; nt < 8; nt++) {
            oacc[nt].x *= sc0;  oacc[nt].y *= sc0;
            oacc[nt].z *= sc1;  oacc[nt].w *= sc1;
        }

        #pragma unroll
        for (int ks = 0; ks < 8; ks++) {
            float x0 = __shfl_sync(0xffffffff, sa[ks].x, lq0);
            float y0 = __shfl_sync(0xffffffff, sa[ks].y, lq0);
            float z0 = __shfl_sync(0xffffffff, sa[ks].z, lq0);
            float w0 = __shfl_sync(0xffffffff, sa[ks].w, lq0);
            float x1 = __shfl_sync(0xffffffff, sa[ks].x, lq1);
            float y1 = __shfl_sync(0xffffffff, sa[ks].y, lq1);
            float z1 = __shfl_sync(0xffffffff, sa[ks].z, lq1);
            float w1 = __shfl_sync(0xffffffff, sa[ks].w, lq1);
            uint32_t pa[4];
            pa[0] = __float_as_uint(rtf32((t & 1) ? y0 : x0));
            pa[1] = __float_as_uint(rtf32((t & 1) ? w0 : z0));
            pa[2] = __float_as_uint(rtf32((t & 1) ? y1 : x1));
            pa[3] = __float_as_uint(rtf32((t & 1) ? w1 : z1));

            const int kr0 = (ks*8 + t    ) * LDV + g;
            const int kr1 = (ks*8 + t + 4) * LDV + g;
            #pragma unroll
            for (int nt = 0; nt < 8; nt++) {
                uint32_t b0 = __float_as_uint(Vb[kr0 + nt*8]);
                uint32_t b1 = __float_as_uint(Vb[kr1 + nt*8]);
                mma8(oacc[nt], pa, b0, b1);
            }
        }
        __syncthreads();
        buf ^= 1;
    }

    const float inv0 = 1.f / l0;
    const float inv1 = 1.f / l1;
    float* o0 = ao + (long)(b*S_ + R0) * D_ + h*HD_;
    float* o1 = ao + (long)(b*S_ + R1) * D_ + h*HD_;
    #pragma unroll
    for (int nt = 0; nt < 8; nt++) {
        *(float2*)(o0 + nt*8 + 2*t) =
            make_float2(rtf32(oacc[nt].x * inv0), rtf32(oacc[nt].y * inv0));
        *(float2*)(o1 + nt*8 + 2*t) =
            make_float2(rtf32(oacc[nt].z * inv1), rtf32(oacc[nt].w * inv1));
    }
}

// ===========================================================================
extern "C" void kernel_launch(void* const* d_in, const int* in_sizes, int n_in,
                              void* d_out, int out_size)
{
    const float* X    = (const float*)d_in[0];
    const float* Wat  = (const float*)d_in[1];
    const float* bat  = (const float*)d_in[2];
    const float* Sp   = (const float*)d_in[3];
    const float* Wp   = (const float*)d_in[4];
    const float* bp   = (const float*)d_in[5];
    float* out = (float*)d_out;

    float *wf, *bf, *x2, *ao, *xr, *wpt;
    cudaGetSymbolAddress((void**)&wf,  g_wf);
    cudaGetSymbolAddress((void**)&bf,  g_bf);
    cudaGetSymbolAddress((void**)&x2,  g_x2);
    cudaGetSymbolAddress((void**)&ao,  g_ao);
    cudaGetSymbolAddress((void**)&xr,  g_xr);
    cudaGetSymbolAddress((void**)&wpt, g_wpt);

    const int gemmSmem = 2 * STG * 128 * LDT * 4;             // 61440 B
    const int attnSmem = 2 * (64*LDK + 64*LDV) * 4;           // 53248 B
    cudaFuncSetAttribute(tf32_gemm_tn,
                         cudaFuncAttributeMaxDynamicSharedMemorySize, gemmSmem);
    cudaFuncSetAttribute(attn_mma,
                         cudaFuncAttributeMaxDynamicSharedMemorySize, attnSmem);

    // 0. ALL prep in one launch
    prep_all<<<NB_ALL, 256>>>(X, Wat, bat, Sp, Wp, xr, wpt, wf, bf);

    // 1. folded QKV GEMM (epilogue rounds x2 to tf32)
    dim3 g1(NF/GBN, M_/GBM);
    tf32_gemm_tn<<<g1, 128, gemmSmem>>>(xr, wf, bf, x2, M_, NF, D_, 1);

    // 2. causal flash attention
    dim3 g3(S_/64, H_, B_);
    attn_mma<<<g3, 128, attnSmem>>>(x2, ao);

    // 3. output projection GEMM (raw fp32 output)
    dim3 g4(D_/GBN, M_/GBM);
    tf32_gemm_tn<<<g4, 128, gemmSmem>>>(ao, wpt, bp, out, M_, D_, D_, 0);
}